// round 2
// baseline (speedup 1.0000x reference)
#include <cuda_runtime.h>
#include <math.h>

#define HID   256
#define ATTN  32
#define MAXU  10000
#define MAXI  30000
#define MAXE  500000
#define MAXN  40000
#define THR   0.8f

// ---------------- scratch (device globals: no allocations allowed) ----------
__device__ float    g_U1[MAXU * ATTN];        // user_emb @ W1[0:256]
__device__ float    g_I1[MAXI * ATTN];        // item_emb @ W1[256:512]
__device__ float    g_w[MAXE];                // raw sigmoid edge weights
__device__ float    g_xw[(size_t)MAXN * HID]; // raw x @ gcn_W
__device__ float    g_deg[MAXN];
__device__ int      g_count;
__device__ unsigned g_maxbits;
__device__ int      g_argidx;

// ---------------- K0: init ---------------------------------------------------
__global__ void init_kernel(int n_nodes) {
    int i = blockIdx.x * blockDim.x + threadIdx.x;
    if (i < n_nodes) g_deg[i] = 1.0f;
    if (i == 0) { g_count = 0; g_maxbits = 0u; g_argidx = 0x7fffffff; }
}

// ---------------- K1: per-node attention projections -------------------------
// row r < n_users : g_U1[r]  = uemb[r] @ W1[0:256]
// row r >= n_users: g_I1[r'] = iemb[r'] @ W1[256:512]
// 8 threads per row, 4 output cols per thread.
__global__ void attn_precompute_kernel(const float* __restrict__ uemb,
                                       const float* __restrict__ iemb,
                                       const float* __restrict__ W1,
                                       int n_users, int n_nodes) {
    int t   = blockIdx.x * blockDim.x + threadIdx.x;
    int row = t >> 3;
    int jg  = (t & 7) * 4;               // output column group
    if (row >= n_nodes) return;

    const float* xrow;
    const float* Wb;
    float*       outp;
    if (row < n_users) {
        xrow = uemb + (size_t)row * HID;
        Wb   = W1;
        outp = g_U1 + (size_t)row * ATTN;
    } else {
        int r = row - n_users;
        xrow = iemb + (size_t)r * HID;
        Wb   = W1 + (size_t)HID * ATTN;  // bottom half
        outp = g_I1 + (size_t)r * ATTN;
    }

    const float4* x4 = (const float4*)xrow;
    float a0 = 0.f, a1 = 0.f, a2 = 0.f, a3 = 0.f;
    #pragma unroll 4
    for (int k4 = 0; k4 < HID / 4; k4++) {
        float4 xv = x4[k4];
        #pragma unroll
        for (int s = 0; s < 4; s++) {
            float xs = (s == 0) ? xv.x : (s == 1) ? xv.y : (s == 2) ? xv.z : xv.w;
            float4 wv = *(const float4*)(Wb + (size_t)(k4 * 4 + s) * ATTN + jg);
            a0 += xs * wv.x; a1 += xs * wv.y; a2 += xs * wv.z; a3 += xs * wv.w;
        }
    }
    outp[jg + 0] = a0; outp[jg + 1] = a1; outp[jg + 2] = a2; outp[jg + 3] = a3;
}

// ---------------- K2: edge weights + count + max -----------------------------
__global__ void edge_weight_kernel(const int* __restrict__ ei,
                                   const float* __restrict__ b1,
                                   const float* __restrict__ W2,
                                   const float* __restrict__ b2,
                                   int n_edges) {
    int e = blockIdx.x * blockDim.x + threadIdx.x;
    bool valid = (e < n_edges);
    float w = 0.f;
    if (valid) {
        int s = ei[e];
        int d = ei[n_edges + e];
        const float4* u4 = (const float4*)(g_U1 + (size_t)s * ATTN);
        const float4* i4 = (const float4*)(g_I1 + (size_t)d * ATTN);
        const float4* b4 = (const float4*)b1;
        const float4* w4 = (const float4*)W2;
        float sum = 0.f;
        #pragma unroll
        for (int q = 0; q < ATTN / 4; q++) {
            float4 a = u4[q], b = i4[q], c = b4[q], v = w4[q];
            float h;
            h = a.x + b.x + c.x; h = (h >= 0.f) ? h : 0.2f * h; sum += h * v.x;
            h = a.y + b.y + c.y; h = (h >= 0.f) ? h : 0.2f * h; sum += h * v.y;
            h = a.z + b.z + c.z; h = (h >= 0.f) ? h : 0.2f * h; sum += h * v.z;
            h = a.w + b.w + c.w; h = (h >= 0.f) ? h : 0.2f * h; sum += h * v.w;
        }
        float z = sum + b2[0];
        w = 1.0f / (1.0f + expf(-z));
        g_w[e] = w;
    }
    // warp-aggregated bookkeeping
    unsigned keepmask = __ballot_sync(0xffffffffu, valid && (w > THR));
    unsigned bits     = valid ? __float_as_uint(w) : 0u; // sigmoid > 0 -> uint-monotone
    unsigned mx       = __reduce_max_sync(0xffffffffu, bits);
    if ((threadIdx.x & 31) == 0) {
        if (keepmask) atomicAdd(&g_count, __popc(keepmask));
        atomicMax(&g_maxbits, mx);
    }
}

// ---------------- K3: first index of max (fallback argmax) -------------------
// Early-outs to a single cached-int read per thread when any edge passed the
// threshold (the overwhelmingly common case).
__global__ void argmax_kernel(int n_edges) {
    if (g_count > 0) return;
    int e = blockIdx.x * blockDim.x + threadIdx.x;
    if (e >= n_edges) return;
    if (__float_as_uint(g_w[e]) == g_maxbits) atomicMin(&g_argidx, e);
}

// ---------------- K4: finalize mask, emit edge output, degrees ---------------
__global__ void finalize_kernel(const int* __restrict__ ei,
                                float* __restrict__ out_edge, int n_edges) {
    int e = blockIdx.x * blockDim.x + threadIdx.x;
    if (e >= n_edges) return;
    float w    = g_w[e];
    bool  keep = (g_count > 0) ? (w > THR) : (e == g_argidx);
    out_edge[e] = keep ? w : 0.0f;
    if (keep) atomicAdd(&g_deg[ei[n_edges + e]], 1.0f);
}

// ---------------- K5: SGEMM xw = X @ W with fused self-loop epilogue ---------
#define BM 128
#define BN 128
#define BK 8
#define TM 8
#define TN 8

__global__ __launch_bounds__(256, 2)
void gemm_xw_kernel(const float* __restrict__ uemb,
                    const float* __restrict__ iemb,
                    const float* __restrict__ W,
                    const float* __restrict__ bias,
                    float* __restrict__ out_gcn,
                    int n_users, int n_nodes) {
    __shared__ float As[BK][BM];
    __shared__ float Bs[BK][BN];

    int tid  = threadIdx.x;
    int row0 = blockIdx.x * BM;
    int col0 = blockIdx.y * BN;

    int a_row = tid >> 1;            // 0..127
    int a_k4  = (tid & 1) * 4;       // 0 or 4
    int b_k   = tid >> 5;            // 0..7
    int b_c   = (tid & 31) * 4;      // 0..124

    int tr = (tid >> 4) * TM;
    int tc = (tid & 15) * TN;

    float acc[TM][TN];
    #pragma unroll
    for (int m = 0; m < TM; m++)
        #pragma unroll
        for (int n = 0; n < TN; n++) acc[m][n] = 0.f;

    int grow = row0 + a_row;
    const float* arow_ptr = nullptr;
    if (grow < n_nodes)
        arow_ptr = (grow < n_users) ? (uemb + (size_t)grow * HID)
                                    : (iemb + (size_t)(grow - n_users) * HID);

    for (int kk = 0; kk < HID; kk += BK) {
        float4 av = make_float4(0.f, 0.f, 0.f, 0.f);
        if (arow_ptr) av = *(const float4*)(arow_ptr + kk + a_k4);
        As[a_k4 + 0][a_row] = av.x;
        As[a_k4 + 1][a_row] = av.y;
        As[a_k4 + 2][a_row] = av.z;
        As[a_k4 + 3][a_row] = av.w;

        float4 bv = *(const float4*)(W + (size_t)(kk + b_k) * HID + col0 + b_c);
        *(float4*)&Bs[b_k][b_c] = bv;
        __syncthreads();

        #pragma unroll
        for (int k = 0; k < BK; k++) {
            float ra[TM], rb[TN];
            #pragma unroll
            for (int m = 0; m < TM; m++) ra[m] = As[k][tr + m];
            #pragma unroll
            for (int n = 0; n < TN; n++) rb[n] = Bs[k][tc + n];
            #pragma unroll
            for (int m = 0; m < TM; m++)
                #pragma unroll
                for (int n = 0; n < TN; n++) acc[m][n] += ra[m] * rb[n];
        }
        __syncthreads();
    }

    // Epilogue: raw xw for the scatter, and scaled (dinv^2 * xw + bias) output.
    #pragma unroll
    for (int m = 0; m < TM; m++) {
        int r = row0 + tr + m;
        if (r >= n_nodes) break;
        float s = 1.0f / g_deg[r];
        float*       orow  = out_gcn + (size_t)r * HID + col0 + tc;
        float*       xwrow = g_xw    + (size_t)r * HID + col0 + tc;
        #pragma unroll
        for (int n = 0; n < TN; n++) {
            float v = acc[m][n];
            xwrow[n] = v;
            orow[n]  = v * s + bias[col0 + tc + n];
        }
    }
}

// ---------------- K6: message scatter (one warp per edge) --------------------
__global__ void scatter_kernel(const int* __restrict__ ei,
                               const float* __restrict__ out_edge,
                               float* __restrict__ out_gcn, int n_edges) {
    int warp = (blockIdx.x * blockDim.x + threadIdx.x) >> 5;
    int lane = threadIdx.x & 31;
    if (warp >= n_edges) return;
    float wv = out_edge[warp];
    if (wv == 0.0f) return;                       // dropped edge
    int s = ei[warp];
    int d = ei[n_edges + warp];
    float coef = rsqrtf(g_deg[s]) * rsqrtf(g_deg[d]);
    const float* xr   = g_xw + (size_t)s * HID;
    float*       orow = out_gcn + (size_t)d * HID;
    #pragma unroll
    for (int i = 0; i < HID / 32; i++)
        atomicAdd(&orow[lane + 32 * i], coef * xr[lane + 32 * i]);
}

// ---------------- launch ------------------------------------------------------
extern "C" void kernel_launch(void* const* d_in, const int* in_sizes, int n_in,
                              void* d_out, int out_size) {
    const float* uemb = (const float*)d_in[0];
    const float* iemb = (const float*)d_in[1];
    const int*   ei   = (const int*)d_in[2];
    const float* W1   = (const float*)d_in[3];
    const float* b1   = (const float*)d_in[4];
    const float* W2   = (const float*)d_in[5];
    const float* b2   = (const float*)d_in[6];
    const float* gW   = (const float*)d_in[7];
    const float* gb   = (const float*)d_in[8];

    int n_users = in_sizes[0] / HID;
    int n_items = in_sizes[1] / HID;
    int n_edges = in_sizes[2] / 2;
    int n_nodes = n_users + n_items;

    float* out_gcn  = (float*)d_out;
    float* out_edge = out_gcn + (size_t)n_nodes * HID;

    init_kernel<<<(n_nodes + 255) / 256, 256>>>(n_nodes);

    attn_precompute_kernel<<<(n_nodes * 8 + 255) / 256, 256>>>(uemb, iemb, W1,
                                                               n_users, n_nodes);

    edge_weight_kernel<<<(n_edges + 255) / 256, 256>>>(ei, b1, W2, b2, n_edges);

    argmax_kernel<<<(n_edges + 255) / 256, 256>>>(n_edges);

    finalize_kernel<<<(n_edges + 255) / 256, 256>>>(ei, out_edge, n_edges);

    dim3 ggrid((n_nodes + BM - 1) / BM, HID / BN);
    gemm_xw_kernel<<<ggrid, 256>>>(uemb, iemb, gW, gb, out_gcn, n_users, n_nodes);

    scatter_kernel<<<(n_edges * 32 + 255) / 256, 256>>>(ei, out_edge, out_gcn,
                                                        n_edges);
}

// round 6
// speedup vs baseline: 1.1606x; 1.1606x over previous
#include <cuda_runtime.h>
#include <math.h>

#define HID   256
#define ATTN  32
#define MAXU  10000
#define MAXI  30000
#define MAXE  500000
#define MAXN  40000
#define THR   0.8f

// ---------------- scratch (device globals: no allocations allowed) ----------
__device__ float    g_U1[MAXU * ATTN];        // user_emb @ W1[0:256]
__device__ float    g_I1[MAXI * ATTN];        // item_emb @ W1[256:512]
__device__ float    g_w[MAXE];                // raw sigmoid edge weights
__device__ float    g_xw[(size_t)MAXN * HID]; // raw x @ gcn_W
__device__ float    g_deg[MAXN];
__device__ int      g_count;
__device__ unsigned g_maxbits;
__device__ int      g_argidx;

// ---------------- K0: init ---------------------------------------------------
__global__ void init_kernel(int n_nodes) {
    int i = blockIdx.x * blockDim.x + threadIdx.x;
    int i4 = i * 4;
    if (i4 < n_nodes) {
        float4 one = make_float4(1.f, 1.f, 1.f, 1.f);
        *(float4*)&g_deg[i4] = one;   // n_nodes = 40000, divisible by 4
    }
    if (i == 0) { g_count = 0; g_maxbits = 0u; g_argidx = 0x7fffffff; }
}

// ---------------- K1: per-node attention projections -------------------------
__global__ void attn_precompute_kernel(const float* __restrict__ uemb,
                                       const float* __restrict__ iemb,
                                       const float* __restrict__ W1,
                                       int n_users, int n_nodes) {
    int t   = blockIdx.x * blockDim.x + threadIdx.x;
    int row = t >> 3;
    int jg  = (t & 7) * 4;               // output column group
    if (row >= n_nodes) return;

    const float* xrow;
    const float* Wb;
    float*       outp;
    if (row < n_users) {
        xrow = uemb + (size_t)row * HID;
        Wb   = W1;
        outp = g_U1 + (size_t)row * ATTN;
    } else {
        int r = row - n_users;
        xrow = iemb + (size_t)r * HID;
        Wb   = W1 + (size_t)HID * ATTN;  // bottom half
        outp = g_I1 + (size_t)r * ATTN;
    }

    const float4* x4 = (const float4*)xrow;
    float a0 = 0.f, a1 = 0.f, a2 = 0.f, a3 = 0.f;
    #pragma unroll 4
    for (int k4 = 0; k4 < HID / 4; k4++) {
        float4 xv = x4[k4];
        #pragma unroll
        for (int s = 0; s < 4; s++) {
            float xs = (s == 0) ? xv.x : (s == 1) ? xv.y : (s == 2) ? xv.z : xv.w;
            float4 wv = *(const float4*)(Wb + (size_t)(k4 * 4 + s) * ATTN + jg);
            a0 += xs * wv.x; a1 += xs * wv.y; a2 += xs * wv.z; a3 += xs * wv.w;
        }
    }
    outp[jg + 0] = a0; outp[jg + 1] = a1; outp[jg + 2] = a2; outp[jg + 3] = a3;
}

// ---------------- K2: edge weights + count + max -----------------------------
__global__ void edge_weight_kernel(const int* __restrict__ ei,
                                   const float* __restrict__ b1,
                                   const float* __restrict__ W2,
                                   const float* __restrict__ b2,
                                   int n_edges) {
    int e = blockIdx.x * blockDim.x + threadIdx.x;
    bool valid = (e < n_edges);
    float w = 0.f;
    if (valid) {
        int s = ei[e];
        int d = ei[n_edges + e];
        const float4* u4 = (const float4*)(g_U1 + (size_t)s * ATTN);
        const float4* i4 = (const float4*)(g_I1 + (size_t)d * ATTN);
        const float4* b4 = (const float4*)b1;
        const float4* w4 = (const float4*)W2;
        float sum = 0.f;
        #pragma unroll
        for (int q = 0; q < ATTN / 4; q++) {
            float4 a = u4[q], b = i4[q], c = b4[q], v = w4[q];
            float h;
            h = a.x + b.x + c.x; h = (h >= 0.f) ? h : 0.2f * h; sum += h * v.x;
            h = a.y + b.y + c.y; h = (h >= 0.f) ? h : 0.2f * h; sum += h * v.y;
            h = a.z + b.z + c.z; h = (h >= 0.f) ? h : 0.2f * h; sum += h * v.z;
            h = a.w + b.w + c.w; h = (h >= 0.f) ? h : 0.2f * h; sum += h * v.w;
        }
        float z = sum + b2[0];
        w = 1.0f / (1.0f + expf(-z));
        g_w[e] = w;
    }
    unsigned keepmask = __ballot_sync(0xffffffffu, valid && (w > THR));
    unsigned bits     = valid ? __float_as_uint(w) : 0u; // sigmoid > 0 -> uint-monotone
    unsigned mx       = __reduce_max_sync(0xffffffffu, bits);
    if ((threadIdx.x & 31) == 0) {
        if (keepmask) atomicAdd(&g_count, __popc(keepmask));
        atomicMax(&g_maxbits, mx);
    }
}

// ---------------- K3: first index of max (fallback argmax) -------------------
__global__ void argmax_kernel(int n_edges) {
    if (g_count > 0) return;
    int e = blockIdx.x * blockDim.x + threadIdx.x;
    if (e >= n_edges) return;
    if (__float_as_uint(g_w[e]) == g_maxbits) atomicMin(&g_argidx, e);
}

// ---------------- K4: finalize mask, emit edge output, degrees ---------------
__global__ void finalize_kernel(const int* __restrict__ ei,
                                float* __restrict__ out_edge, int n_edges) {
    int e = blockIdx.x * blockDim.x + threadIdx.x;
    if (e >= n_edges) return;
    float w    = g_w[e];
    bool  keep = (g_count > 0) ? (w > THR) : (e == g_argidx);
    out_edge[e] = keep ? w : 0.0f;
    if (keep) atomicAdd(&g_deg[ei[n_edges + e]], 1.0f);  // dst load only when kept
}

// ---------------- K5: SGEMM xw = X @ W, double-buffered BK=16 ----------------
#define BM 128
#define BN 128
#define BK 16
#define TM 8
#define TN 8

__global__ __launch_bounds__(256, 2)
void gemm_xw_kernel(const float* __restrict__ uemb,
                    const float* __restrict__ iemb,
                    const float* __restrict__ W,
                    const float* __restrict__ bias,
                    float* __restrict__ out_gcn,
                    int n_users, int n_nodes) {
    __shared__ float As[2][BK][BM + 4];
    __shared__ float Bs[2][BK][BN];

    int tid  = threadIdx.x;
    int row0 = blockIdx.x * BM;
    int col0 = blockIdx.y * BN;

    // A load map: thread loads 2 consecutive float4 (8 floats) of one row.
    int a_row = tid >> 1;            // 0..127
    int a_k8  = (tid & 1) * 8;       // 0 or 8
    // B load map: thread loads 8 consecutive floats of one k-row.
    int b_k   = tid >> 4;            // 0..15
    int b_c   = (tid & 15) * 8;      // 0..120

    int tr = (tid >> 4) * TM;
    int tc = (tid & 15) * TN;

    float acc[TM][TN];
    #pragma unroll
    for (int m = 0; m < TM; m++)
        #pragma unroll
        for (int n = 0; n < TN; n++) acc[m][n] = 0.f;

    int grow = row0 + a_row;
    const float* arow_ptr = nullptr;
    if (grow < n_nodes)
        arow_ptr = (grow < n_users) ? (uemb + (size_t)grow * HID)
                                    : (iemb + (size_t)(grow - n_users) * HID);
    const float* brow_ptr = W + (size_t)b_k * HID + col0 + b_c;

    const int NT = HID / BK;   // 16 tiles

    // prologue: load tile 0
    {
        float4 av0 = make_float4(0.f,0.f,0.f,0.f), av1 = av0;
        if (arow_ptr) {
            av0 = *(const float4*)(arow_ptr + a_k8);
            av1 = *(const float4*)(arow_ptr + a_k8 + 4);
        }
        As[0][a_k8 + 0][a_row] = av0.x; As[0][a_k8 + 1][a_row] = av0.y;
        As[0][a_k8 + 2][a_row] = av0.z; As[0][a_k8 + 3][a_row] = av0.w;
        As[0][a_k8 + 4][a_row] = av1.x; As[0][a_k8 + 5][a_row] = av1.y;
        As[0][a_k8 + 6][a_row] = av1.z; As[0][a_k8 + 7][a_row] = av1.w;
        float4 bv0 = *(const float4*)(brow_ptr);
        float4 bv1 = *(const float4*)(brow_ptr + 4);
        *(float4*)&Bs[0][b_k][b_c]     = bv0;
        *(float4*)&Bs[0][b_k][b_c + 4] = bv1;
    }
    __syncthreads();

    int cur = 0;
    for (int t = 0; t < NT; t++) {
        float4 av0, av1, bv0, bv1;
        bool has_next = (t + 1 < NT);
        if (has_next) {
            int kk = (t + 1) * BK;
            av0 = make_float4(0.f,0.f,0.f,0.f); av1 = av0;
            if (arow_ptr) {
                av0 = *(const float4*)(arow_ptr + kk + a_k8);
                av1 = *(const float4*)(arow_ptr + kk + a_k8 + 4);
            }
            bv0 = *(const float4*)(brow_ptr + (size_t)kk * HID);
            bv1 = *(const float4*)(brow_ptr + (size_t)kk * HID + 4);
        }

        #pragma unroll
        for (int k = 0; k < BK; k++) {
            float ra[TM];
            float rb[TN];
            #pragma unroll
            for (int m = 0; m < TM; m++) ra[m] = As[cur][k][tr + m];
            float4 rb0 = *(const float4*)&Bs[cur][k][tc];
            float4 rb1 = *(const float4*)&Bs[cur][k][tc + 4];
            rb[0]=rb0.x; rb[1]=rb0.y; rb[2]=rb0.z; rb[3]=rb0.w;
            rb[4]=rb1.x; rb[5]=rb1.y; rb[6]=rb1.z; rb[7]=rb1.w;
            #pragma unroll
            for (int m = 0; m < TM; m++)
                #pragma unroll
                for (int n = 0; n < TN; n++) acc[m][n] += ra[m] * rb[n];
        }

        if (has_next) {
            int nxt = cur ^ 1;
            As[nxt][a_k8 + 0][a_row] = av0.x; As[nxt][a_k8 + 1][a_row] = av0.y;
            As[nxt][a_k8 + 2][a_row] = av0.z; As[nxt][a_k8 + 3][a_row] = av0.w;
            As[nxt][a_k8 + 4][a_row] = av1.x; As[nxt][a_k8 + 5][a_row] = av1.y;
            As[nxt][a_k8 + 6][a_row] = av1.z; As[nxt][a_k8 + 7][a_row] = av1.w;
            *(float4*)&Bs[nxt][b_k][b_c]     = bv0;
            *(float4*)&Bs[nxt][b_k][b_c + 4] = bv1;
            __syncthreads();
            cur = nxt;
        }
    }

    // Epilogue: raw xw for the scatter, and scaled (dinv^2 * xw + bias) output.
    #pragma unroll
    for (int m = 0; m < TM; m++) {
        int r = row0 + tr + m;
        if (r >= n_nodes) break;
        float s = 1.0f / g_deg[r];
        float*       orow  = out_gcn + (size_t)r * HID + col0 + tc;
        float*       xwrow = g_xw    + (size_t)r * HID + col0 + tc;
        #pragma unroll
        for (int n = 0; n < TN; n += 4) {
            float4 v = make_float4(acc[m][n], acc[m][n+1], acc[m][n+2], acc[m][n+3]);
            *(float4*)(xwrow + n) = v;
            float4 b = *(const float4*)(bias + col0 + tc + n);
            float4 o = make_float4(v.x * s + b.x, v.y * s + b.y,
                                   v.z * s + b.z, v.w * s + b.w);
            *(float4*)(orow + n) = o;
        }
    }
}

// ---------------- K6: message scatter (one warp per edge, v4 reductions) -----
__global__ void scatter_kernel(const int* __restrict__ ei,
                               const float* __restrict__ out_edge,
                               float* __restrict__ out_gcn, int n_edges) {
    int warp = (blockIdx.x * blockDim.x + threadIdx.x) >> 5;
    int lane = threadIdx.x & 31;
    if (warp >= n_edges) return;
    float wv = out_edge[warp];
    if (wv == 0.0f) return;                       // dropped edge
    int s = ei[warp];
    int d = ei[n_edges + warp];
    float coef = rsqrtf(g_deg[s]) * rsqrtf(g_deg[d]);
    const float4* xr   = (const float4*)(g_xw + (size_t)s * HID);
    float4*       orow = (float4*)(out_gcn + (size_t)d * HID);
    #pragma unroll
    for (int i = 0; i < HID / 128; i++) {        // 2 float4 per lane
        float4 v = xr[lane + 32 * i];
        v.x *= coef; v.y *= coef; v.z *= coef; v.w *= coef;
        asm volatile("red.global.add.v4.f32 [%0], {%1, %2, %3, %4};"
                     :: "l"(&orow[lane + 32 * i]),
                        "f"(v.x), "f"(v.y), "f"(v.z), "f"(v.w)
                     : "memory");
    }
}

// ---------------- launch ------------------------------------------------------
extern "C" void kernel_launch(void* const* d_in, const int* in_sizes, int n_in,
                              void* d_out, int out_size) {
    const float* uemb = (const float*)d_in[0];
    const float* iemb = (const float*)d_in[1];
    const int*   ei   = (const int*)d_in[2];
    const float* W1   = (const float*)d_in[3];
    const float* b1   = (const float*)d_in[4];
    const float* W2   = (const float*)d_in[5];
    const float* b2   = (const float*)d_in[6];
    const float* gW   = (const float*)d_in[7];
    const float* gb   = (const float*)d_in[8];

    int n_users = in_sizes[0] / HID;
    int n_items = in_sizes[1] / HID;
    int n_edges = in_sizes[2] / 2;
    int n_nodes = n_users + n_items;

    float* out_gcn  = (float*)d_out;
    float* out_edge = out_gcn + (size_t)n_nodes * HID;

    init_kernel<<<(n_nodes / 4 + 255) / 256, 256>>>(n_nodes);

    attn_precompute_kernel<<<(n_nodes * 8 + 255) / 256, 256>>>(uemb, iemb, W1,
                                                               n_users, n_nodes);

    edge_weight_kernel<<<(n_edges + 255) / 256, 256>>>(ei, b1, W2, b2, n_edges);

    argmax_kernel<<<(n_edges + 255) / 256, 256>>>(n_edges);

    finalize_kernel<<<(n_edges + 255) / 256, 256>>>(ei, out_edge, n_edges);

    dim3 ggrid((n_nodes + BM - 1) / BM, HID / BN);
    gemm_xw_kernel<<<ggrid, 256>>>(uemb, iemb, gW, gb, out_gcn, n_users, n_nodes);

    scatter_kernel<<<(n_edges * 32 + 255) / 256, 256>>>(ei, out_edge, out_gcn,
                                                        n_edges);
}

// round 8
// speedup vs baseline: 1.4696x; 1.2662x over previous
#include <cuda_runtime.h>
#include <cuda_bf16.h>
#include <math.h>

#define HID   256
#define ATTN  32
#define MAXU  10000
#define MAXI  30000
#define MAXE  500000
#define MAXN  40000
#define MPAD  40960          // 320 * 128, padded M for the GEMM
#define THR   0.8f

// ---------------- scratch (device globals: no allocations allowed) ----------
__device__ float         g_U1[MAXU * ATTN];
__device__ float         g_I1[MAXI * ATTN];
__device__ float         g_w[MAXE];
__device__ float         g_xw[(size_t)MAXN * HID];
__device__ float         g_deg[MAXN];
__device__ int           g_count;
__device__ unsigned      g_maxbits;
__device__ int           g_argidx;
// split-bf16 GEMM operands
__device__ __nv_bfloat16 g_Ahi[(size_t)MPAD * HID];
__device__ __nv_bfloat16 g_Alo[(size_t)MPAD * HID];
__device__ __nv_bfloat16 g_Bhi[HID * HID];   // W^T  [n][k]
__device__ __nv_bfloat16 g_Blo[HID * HID];   // W^T  [n][k]

// ---------------- K0: init ---------------------------------------------------
__global__ void init_kernel(int n_nodes) {
    int i = blockIdx.x * blockDim.x + threadIdx.x;
    int i4 = i * 4;
    if (i4 < n_nodes) {
        float4 one = make_float4(1.f, 1.f, 1.f, 1.f);
        *(float4*)&g_deg[i4] = one;
    }
    if (i == 0) { g_count = 0; g_maxbits = 0u; g_argidx = 0x7fffffff; }
}

// ---------------- K1: split-bf16 conversion of X (user||item, zero-padded) ---
__global__ void convert_x_kernel(const float* __restrict__ uemb,
                                 const float* __restrict__ iemb,
                                 int n_users, int n_nodes) {
    int t   = blockIdx.x * blockDim.x + threadIdx.x;
    int row = t >> 5;                    // 32 threads per 256-wide row
    int kc  = (t & 31) * 8;
    if (row >= MPAD) return;

    float f[8];
    if (row < n_nodes) {
        const float* p = (row < n_users)
            ? (uemb + (size_t)row * HID + kc)
            : (iemb + (size_t)(row - n_users) * HID + kc);
        float4 v0 = *(const float4*)p;
        float4 v1 = *(const float4*)(p + 4);
        f[0]=v0.x; f[1]=v0.y; f[2]=v0.z; f[3]=v0.w;
        f[4]=v1.x; f[5]=v1.y; f[6]=v1.z; f[7]=v1.w;
    } else {
        #pragma unroll
        for (int i = 0; i < 8; i++) f[i] = 0.f;
    }

    unsigned hip[4], lop[4];
    #pragma unroll
    for (int i = 0; i < 4; i++) {
        __nv_bfloat162 h = __floats2bfloat162_rn(f[2*i], f[2*i+1]);
        hip[i] = *(unsigned*)&h;
        __nv_bfloat162 l = __floats2bfloat162_rn(
            f[2*i]   - __bfloat162float(__low2bfloat16(h)),
            f[2*i+1] - __bfloat162float(__high2bfloat16(h)));
        lop[i] = *(unsigned*)&l;
    }
    size_t off = (size_t)row * HID + kc;
    *(uint4*)&g_Ahi[off] = make_uint4(hip[0], hip[1], hip[2], hip[3]);
    *(uint4*)&g_Alo[off] = make_uint4(lop[0], lop[1], lop[2], lop[3]);
}

// ---------------- K1b: split-bf16 transpose of W -----------------------------
__global__ void convert_w_kernel(const float* __restrict__ W) {
    int t = blockIdx.x * blockDim.x + threadIdx.x;   // 65536 threads
    if (t >= HID * HID) return;
    int k = t >> 8, n = t & 255;
    float x = W[t];                                  // W[k][n], coalesced read
    __nv_bfloat16 h = __float2bfloat16_rn(x);
    __nv_bfloat16 l = __float2bfloat16_rn(x - __bfloat162float(h));
    g_Bhi[n * HID + k] = h;
    g_Blo[n * HID + k] = l;
}

// ---------------- K2: per-node attention projections -------------------------
__global__ void attn_precompute_kernel(const float* __restrict__ uemb,
                                       const float* __restrict__ iemb,
                                       const float* __restrict__ W1,
                                       int n_users, int n_nodes) {
    int t   = blockIdx.x * blockDim.x + threadIdx.x;
    int row = t >> 3;
    int jg  = (t & 7) * 4;
    if (row >= n_nodes) return;

    const float* xrow;
    const float* Wb;
    float*       outp;
    if (row < n_users) {
        xrow = uemb + (size_t)row * HID;
        Wb   = W1;
        outp = g_U1 + (size_t)row * ATTN;
    } else {
        int r = row - n_users;
        xrow = iemb + (size_t)r * HID;
        Wb   = W1 + (size_t)HID * ATTN;
        outp = g_I1 + (size_t)r * ATTN;
    }

    const float4* x4 = (const float4*)xrow;
    float a0 = 0.f, a1 = 0.f, a2 = 0.f, a3 = 0.f;
    #pragma unroll 4
    for (int k4 = 0; k4 < HID / 4; k4++) {
        float4 xv = x4[k4];
        #pragma unroll
        for (int s = 0; s < 4; s++) {
            float xs = (s == 0) ? xv.x : (s == 1) ? xv.y : (s == 2) ? xv.z : xv.w;
            float4 wv = *(const float4*)(Wb + (size_t)(k4 * 4 + s) * ATTN + jg);
            a0 += xs * wv.x; a1 += xs * wv.y; a2 += xs * wv.z; a3 += xs * wv.w;
        }
    }
    outp[jg + 0] = a0; outp[jg + 1] = a1; outp[jg + 2] = a2; outp[jg + 3] = a3;
}

// ---------------- K3: edge weights + count + max -----------------------------
__global__ void edge_weight_kernel(const int* __restrict__ ei,
                                   const float* __restrict__ b1,
                                   const float* __restrict__ W2,
                                   const float* __restrict__ b2,
                                   int n_edges) {
    int e = blockIdx.x * blockDim.x + threadIdx.x;
    bool valid = (e < n_edges);
    float w = 0.f;
    if (valid) {
        int s = ei[e];
        int d = ei[n_edges + e];
        const float4* u4 = (const float4*)(g_U1 + (size_t)s * ATTN);
        const float4* i4 = (const float4*)(g_I1 + (size_t)d * ATTN);
        const float4* b4 = (const float4*)b1;
        const float4* w4 = (const float4*)W2;
        float sum = 0.f;
        #pragma unroll
        for (int q = 0; q < ATTN / 4; q++) {
            float4 a = u4[q], b = i4[q], c = b4[q], v = w4[q];
            float h;
            h = a.x + b.x + c.x; h = (h >= 0.f) ? h : 0.2f * h; sum += h * v.x;
            h = a.y + b.y + c.y; h = (h >= 0.f) ? h : 0.2f * h; sum += h * v.y;
            h = a.z + b.z + c.z; h = (h >= 0.f) ? h : 0.2f * h; sum += h * v.z;
            h = a.w + b.w + c.w; h = (h >= 0.f) ? h : 0.2f * h; sum += h * v.w;
        }
        float z = sum + b2[0];
        w = 1.0f / (1.0f + expf(-z));
        g_w[e] = w;
    }
    unsigned keepmask = __ballot_sync(0xffffffffu, valid && (w > THR));
    unsigned bits     = valid ? __float_as_uint(w) : 0u;
    unsigned mx       = __reduce_max_sync(0xffffffffu, bits);
    if ((threadIdx.x & 31) == 0) {
        if (keepmask) atomicAdd(&g_count, __popc(keepmask));
        atomicMax(&g_maxbits, mx);
    }
}

// ---------------- K4: first index of max (fallback argmax) -------------------
__global__ void argmax_kernel(int n_edges) {
    if (g_count > 0) return;
    int e = blockIdx.x * blockDim.x + threadIdx.x;
    if (e >= n_edges) return;
    if (__float_as_uint(g_w[e]) == g_maxbits) atomicMin(&g_argidx, e);
}

// ---------------- K5: finalize mask, emit edge output, degrees ---------------
__global__ void finalize_kernel(const int* __restrict__ ei,
                                float* __restrict__ out_edge, int n_edges) {
    int e = blockIdx.x * blockDim.x + threadIdx.x;
    if (e >= n_edges) return;
    float w    = g_w[e];
    bool  keep = (g_count > 0) ? (w > THR) : (e == g_argidx);
    out_edge[e] = keep ? w : 0.0f;
    if (keep) atomicAdd(&g_deg[ei[n_edges + e]], 1.0f);
}

// ---------------- K6: split-bf16 HMMA GEMM  xw = X @ W -----------------------
// C = Ahi*Bhi + Ahi*Blo + Alo*Bhi   (3 passes over K=256, bf16, fp32 accum)
#define GBM 128
#define GBN 128
#define GBK 32
#define BKP 40            // padded smem k-stride (bf16): conflict-free frags

__global__ __launch_bounds__(256, 2)
void gemm_bf16_kernel(const float* __restrict__ bias,
                      float* __restrict__ out_gcn, int n_nodes) {
    __shared__ __nv_bfloat16 As[2][GBM * BKP];
    __shared__ __nv_bfloat16 Bs[2][GBN * BKP];

    const int tid  = threadIdx.x;
    const int warp = tid >> 5;
    const int lane = tid & 31;
    const int wr   = warp >> 2;          // 0..1  (64-row warp tiles)
    const int wc   = warp & 3;           // 0..3  (32-col warp tiles)
    const int grp  = lane >> 2;          // 0..7
    const int tq   = lane & 3;           // 0..3
    const int row0 = blockIdx.x * GBM;
    const int col0 = blockIdx.y * GBN;

    // gmem->smem staging map: two rows per thread, 8 bf16 chunk
    const int lr = tid >> 2;             // 0..63
    const int lc = (tid & 3) * 8;        // 0,8,16,24

    float acc[4][4][4];
    #pragma unroll
    for (int mf = 0; mf < 4; mf++)
        #pragma unroll
        for (int nf = 0; nf < 4; nf++)
            #pragma unroll
            for (int c = 0; c < 4; c++) acc[mf][nf][c] = 0.f;

    const int NT = 3 * (HID / GBK);      // 24 tiles

    uint4 ra0, ra1, rb0, rb1;
    // ---- load tile t into registers
    auto ldg_tile = [&](int t, uint4& a0, uint4& a1, uint4& b0, uint4& b1) {
        int pass = t >> 3;
        int kk   = (t & 7) * GBK;
        const __nv_bfloat16* Ap = (pass == 2) ? g_Alo : g_Ahi;
        const __nv_bfloat16* Bp = (pass == 1) ? g_Blo : g_Bhi;
        a0 = *(const uint4*)(Ap + (size_t)(row0 + lr)      * HID + kk + lc);
        a1 = *(const uint4*)(Ap + (size_t)(row0 + lr + 64) * HID + kk + lc);
        b0 = *(const uint4*)(Bp + (size_t)(col0 + lr)      * HID + kk + lc);
        b1 = *(const uint4*)(Bp + (size_t)(col0 + lr + 64) * HID + kk + lc);
    };
    // ---- store registers into smem buffer (8B stores: BKP*2 is 8B-multiple)
    auto sts_tile = [&](int buf, uint4 a0, uint4 a1, uint4 b0, uint4 b1) {
        uint2* pa0 = (uint2*)&As[buf][lr * BKP + lc];
        pa0[0] = make_uint2(a0.x, a0.y); pa0[1] = make_uint2(a0.z, a0.w);
        uint2* pa1 = (uint2*)&As[buf][(lr + 64) * BKP + lc];
        pa1[0] = make_uint2(a1.x, a1.y); pa1[1] = make_uint2(a1.z, a1.w);
        uint2* pb0 = (uint2*)&Bs[buf][lr * BKP + lc];
        pb0[0] = make_uint2(b0.x, b0.y); pb0[1] = make_uint2(b0.z, b0.w);
        uint2* pb1 = (uint2*)&Bs[buf][(lr + 64) * BKP + lc];
        pb1[0] = make_uint2(b1.x, b1.y); pb1[1] = make_uint2(b1.z, b1.w);
    };

    ldg_tile(0, ra0, ra1, rb0, rb1);
    sts_tile(0, ra0, ra1, rb0, rb1);
    __syncthreads();

    int cur = 0;
    for (int t = 0; t < NT; t++) {
        bool has_next = (t + 1 < NT);
        if (has_next) ldg_tile(t + 1, ra0, ra1, rb0, rb1);

        #pragma unroll
        for (int ks = 0; ks < 2; ks++) {
            int k0 = ks * 16;
            unsigned afr[4][4], bfr[4][2];
            #pragma unroll
            for (int mf = 0; mf < 4; mf++) {
                const __nv_bfloat16* ab =
                    &As[cur][(wr * 64 + mf * 16 + grp) * BKP + k0 + 2 * tq];
                afr[mf][0] = *(const unsigned*)(ab);
                afr[mf][1] = *(const unsigned*)(ab + 8 * BKP);
                afr[mf][2] = *(const unsigned*)(ab + 8);
                afr[mf][3] = *(const unsigned*)(ab + 8 * BKP + 8);
            }
            #pragma unroll
            for (int nf = 0; nf < 4; nf++) {
                const __nv_bfloat16* bb =
                    &Bs[cur][(wc * 32 + nf * 8 + grp) * BKP + k0 + 2 * tq];
                bfr[nf][0] = *(const unsigned*)(bb);
                bfr[nf][1] = *(const unsigned*)(bb + 8);
            }
            #pragma unroll
            for (int mf = 0; mf < 4; mf++)
                #pragma unroll
                for (int nf = 0; nf < 4; nf++) {
                    float* c = acc[mf][nf];
                    asm volatile(
                        "mma.sync.aligned.m16n8k16.row.col.f32.bf16.bf16.f32 "
                        "{%0,%1,%2,%3}, {%4,%5,%6,%7}, {%8,%9}, {%0,%1,%2,%3};"
                        : "+f"(c[0]), "+f"(c[1]), "+f"(c[2]), "+f"(c[3])
                        : "r"(afr[mf][0]), "r"(afr[mf][1]),
                          "r"(afr[mf][2]), "r"(afr[mf][3]),
                          "r"(bfr[nf][0]), "r"(bfr[nf][1]));
                }
        }

        if (has_next) {
            int nxt = cur ^ 1;
            sts_tile(nxt, ra0, ra1, rb0, rb1);
            __syncthreads();
            cur = nxt;
        }
    }

    // Epilogue: raw xw + scaled (deg^-1 * xw + bias) output.
    #pragma unroll
    for (int mf = 0; mf < 4; mf++) {
        int r1 = row0 + wr * 64 + mf * 16 + grp;
        int r2 = r1 + 8;
        float s1 = (r1 < n_nodes) ? (1.0f / g_deg[r1]) : 0.f;
        float s2 = (r2 < n_nodes) ? (1.0f / g_deg[r2]) : 0.f;
        #pragma unroll
        for (int nf = 0; nf < 4; nf++) {
            int cc = col0 + wc * 32 + nf * 8 + 2 * tq;
            float2 b = *(const float2*)(bias + cc);
            const float* c = acc[mf][nf];
            if (r1 < n_nodes) {
                *(float2*)(g_xw    + (size_t)r1 * HID + cc) = make_float2(c[0], c[1]);
                *(float2*)(out_gcn + (size_t)r1 * HID + cc) =
                    make_float2(c[0] * s1 + b.x, c[1] * s1 + b.y);
            }
            if (r2 < n_nodes) {
                *(float2*)(g_xw    + (size_t)r2 * HID + cc) = make_float2(c[2], c[3]);
                *(float2*)(out_gcn + (size_t)r2 * HID + cc) =
                    make_float2(c[2] * s2 + b.x, c[3] * s2 + b.y);
            }
        }
    }
}

// ---------------- K7: message scatter (one warp per edge, v4 reductions) -----
__global__ void scatter_kernel(const int* __restrict__ ei,
                               const float* __restrict__ out_edge,
                               float* __restrict__ out_gcn, int n_edges) {
    int warp = (blockIdx.x * blockDim.x + threadIdx.x) >> 5;
    int lane = threadIdx.x & 31;
    if (warp >= n_edges) return;
    float wv = out_edge[warp];
    if (wv == 0.0f) return;
    int s = ei[warp];
    int d = ei[n_edges + warp];
    float coef = rsqrtf(g_deg[s]) * rsqrtf(g_deg[d]);
    const float4* xr   = (const float4*)(g_xw + (size_t)s * HID);
    float4*       orow = (float4*)(out_gcn + (size_t)d * HID);
    #pragma unroll
    for (int i = 0; i < HID / 128; i++) {
        float4 v = xr[lane + 32 * i];
        v.x *= coef; v.y *= coef; v.z *= coef; v.w *= coef;
        asm volatile("red.global.add.v4.f32 [%0], {%1, %2, %3, %4};"
                     :: "l"(&orow[lane + 32 * i]),
                        "f"(v.x), "f"(v.y), "f"(v.z), "f"(v.w)
                     : "memory");
    }
}

// ---------------- launch ------------------------------------------------------
extern "C" void kernel_launch(void* const* d_in, const int* in_sizes, int n_in,
                              void* d_out, int out_size) {
    const float* uemb = (const float*)d_in[0];
    const float* iemb = (const float*)d_in[1];
    const int*   ei   = (const int*)d_in[2];
    const float* W1   = (const float*)d_in[3];
    const float* b1   = (const float*)d_in[4];
    const float* W2   = (const float*)d_in[5];
    const float* b2   = (const float*)d_in[6];
    const float* gW   = (const float*)d_in[7];
    const float* gb   = (const float*)d_in[8];

    int n_users = in_sizes[0] / HID;
    int n_items = in_sizes[1] / HID;
    int n_edges = in_sizes[2] / 2;
    int n_nodes = n_users + n_items;

    float* out_gcn  = (float*)d_out;
    float* out_edge = out_gcn + (size_t)n_nodes * HID;

    init_kernel<<<(n_nodes / 4 + 255) / 256, 256>>>(n_nodes);

    convert_x_kernel<<<(MPAD * 32) / 256, 256>>>(uemb, iemb, n_users, n_nodes);
    convert_w_kernel<<<(HID * HID) / 256, 256>>>(gW);

    attn_precompute_kernel<<<(n_nodes * 8 + 255) / 256, 256>>>(uemb, iemb, W1,
                                                               n_users, n_nodes);

    edge_weight_kernel<<<(n_edges + 255) / 256, 256>>>(ei, b1, W2, b2, n_edges);

    argmax_kernel<<<(n_edges + 255) / 256, 256>>>(n_edges);

    finalize_kernel<<<(n_edges + 255) / 256, 256>>>(ei, out_edge, n_edges);

    dim3 ggrid(MPAD / GBM, HID / GBN);
    gemm_bf16_kernel<<<ggrid, 256>>>(gb, out_gcn, n_nodes);

    scatter_kernel<<<(n_edges * 32 + 255) / 256, 256>>>(ei, out_edge, out_gcn,
                                                        n_edges);
}

// round 10
// speedup vs baseline: 1.6556x; 1.1266x over previous
#include <cuda_runtime.h>
#include <cuda_bf16.h>
#include <math.h>

#define HID   256
#define ATTN  32
#define MAXU  10000
#define MAXI  30000
#define MAXE  500000
#define MAXN  40000
#define MPAD  40960          // 320 * 128, padded M for the GEMM
#define THR   0.8f

// ---------------- scratch (device globals: no allocations allowed) ----------
__device__ float         g_U1[MAXU * ATTN];
__device__ float         g_I1[MAXI * ATTN];
__device__ float         g_w[MAXE];
__device__ float         g_xw[(size_t)MAXN * HID];
__device__ float         g_deg[MAXN];
__device__ int           g_count;
__device__ unsigned      g_maxbits;
__device__ int           g_argidx;
// split-bf16 GEMM operands
__device__ __nv_bfloat16 g_Ahi[(size_t)MPAD * HID];
__device__ __nv_bfloat16 g_Alo[(size_t)MPAD * HID];
__device__ __nv_bfloat16 g_Bhi[HID * HID];   // W^T  [n][k]
__device__ __nv_bfloat16 g_Blo[HID * HID];   // W^T  [n][k]

// ---------------- K0: init ---------------------------------------------------
__global__ void init_kernel(int n_nodes) {
    int i = blockIdx.x * blockDim.x + threadIdx.x;
    int i4 = i * 4;
    if (i4 < n_nodes) {
        float4 one = make_float4(1.f, 1.f, 1.f, 1.f);
        *(float4*)&g_deg[i4] = one;
    }
    if (i == 0) { g_count = 0; g_maxbits = 0u; g_argidx = 0x7fffffff; }
}

// ---------------- K1: split-bf16 conversion of X (user||item, zero-padded) ---
__global__ void convert_x_kernel(const float* __restrict__ uemb,
                                 const float* __restrict__ iemb,
                                 int n_users, int n_nodes) {
    int t   = blockIdx.x * blockDim.x + threadIdx.x;
    int row = t >> 5;                    // 32 threads per 256-wide row
    int kc  = (t & 31) * 8;
    if (row >= MPAD) return;

    float f[8];
    if (row < n_nodes) {
        const float* p = (row < n_users)
            ? (uemb + (size_t)row * HID + kc)
            : (iemb + (size_t)(row - n_users) * HID + kc);
        float4 v0 = *(const float4*)p;
        float4 v1 = *(const float4*)(p + 4);
        f[0]=v0.x; f[1]=v0.y; f[2]=v0.z; f[3]=v0.w;
        f[4]=v1.x; f[5]=v1.y; f[6]=v1.z; f[7]=v1.w;
    } else {
        #pragma unroll
        for (int i = 0; i < 8; i++) f[i] = 0.f;
    }

    unsigned hip[4], lop[4];
    #pragma unroll
    for (int i = 0; i < 4; i++) {
        __nv_bfloat162 h = __floats2bfloat162_rn(f[2*i], f[2*i+1]);
        hip[i] = *(unsigned*)&h;
        __nv_bfloat162 l = __floats2bfloat162_rn(
            f[2*i]   - __bfloat162float(__low2bfloat16(h)),
            f[2*i+1] - __bfloat162float(__high2bfloat16(h)));
        lop[i] = *(unsigned*)&l;
    }
    size_t off = (size_t)row * HID + kc;
    *(uint4*)&g_Ahi[off] = make_uint4(hip[0], hip[1], hip[2], hip[3]);
    *(uint4*)&g_Alo[off] = make_uint4(lop[0], lop[1], lop[2], lop[3]);
}

// ---------------- K1b: split-bf16 transpose of W -----------------------------
__global__ void convert_w_kernel(const float* __restrict__ W) {
    int t = blockIdx.x * blockDim.x + threadIdx.x;   // 65536 threads
    if (t >= HID * HID) return;
    int k = t >> 8, n = t & 255;
    float x = W[t];                                  // W[k][n], coalesced read
    __nv_bfloat16 h = __float2bfloat16_rn(x);
    __nv_bfloat16 l = __float2bfloat16_rn(x - __bfloat162float(h));
    g_Bhi[n * HID + k] = h;
    g_Blo[n * HID + k] = l;
}

// ---------------- K2: attention projections, smem-tiled GEMM -----------------
// Per block: 128 rows x 32 cols of one node type (uniform W1 half).
// Grid: [0, UBLK) -> user rows, [UBLK, UBLK+IBLK) -> item rows.
#define ABM 128
#define ABK 32
#define XPAD 4               // row stride 36 floats = 144 B: 16B-aligned float4s

__global__ __launch_bounds__(256, 2)
void attn_precompute_kernel(const float* __restrict__ uemb,
                            const float* __restrict__ iemb,
                            const float* __restrict__ W1,
                            int n_users, int n_items, int ublk) {
    __shared__ float Xs[ABM][ABK + XPAD];   // 18 KB
    __shared__ float Ws[ABK][ATTN];         // 4 KB

    int b = blockIdx.x;
    const float* X;
    const float* Wb;
    float*       out;
    int          nrows, row0;
    if (b < ublk) {
        X = uemb; Wb = W1;                      out = g_U1;
        nrows = n_users; row0 = b * ABM;
    } else {
        X = iemb; Wb = W1 + (size_t)HID * ATTN; out = g_I1;
        nrows = n_items; row0 = (b - ublk) * ABM;
    }

    int tid = threadIdx.x;
    // X stage map: 2 threads per row, 16 floats each
    int lxr = tid >> 1;            // 0..127
    int lxc = (tid & 1) * 16;      // 0 or 16
    // W stage map: 4 floats per thread
    int lwr = tid >> 3;            // 0..31
    int lwc = (tid & 7) * 4;       // 0..28
    // compute map: 4 rows x 4 cols per thread
    int tr = (tid >> 3) * 4;       // 0..124
    int tc = (tid & 7) * 4;        // 0..28

    float acc[4][4];
    #pragma unroll
    for (int m = 0; m < 4; m++)
        #pragma unroll
        for (int n = 0; n < 4; n++) acc[m][n] = 0.f;

    int xrow = row0 + lxr;
    const float* xp = (xrow < nrows) ? (X + (size_t)xrow * HID) : nullptr;

    for (int kk = 0; kk < HID; kk += ABK) {
        // stage X tile
        float4 v0 = make_float4(0.f,0.f,0.f,0.f), v1 = v0, v2 = v0, v3 = v0;
        if (xp) {
            v0 = *(const float4*)(xp + kk + lxc);
            v1 = *(const float4*)(xp + kk + lxc + 4);
            v2 = *(const float4*)(xp + kk + lxc + 8);
            v3 = *(const float4*)(xp + kk + lxc + 12);
        }
        *(float4*)&Xs[lxr][lxc]      = v0;
        *(float4*)&Xs[lxr][lxc + 4]  = v1;
        *(float4*)&Xs[lxr][lxc + 8]  = v2;
        *(float4*)&Xs[lxr][lxc + 12] = v3;
        // stage W chunk
        *(float4*)&Ws[lwr][lwc] =
            *(const float4*)(Wb + (size_t)(kk + lwr) * ATTN + lwc);
        __syncthreads();

        #pragma unroll
        for (int k = 0; k < ABK; k++) {
            float  ra0 = Xs[tr + 0][k], ra1 = Xs[tr + 1][k];
            float  ra2 = Xs[tr + 2][k], ra3 = Xs[tr + 3][k];
            float4 rb  = *(const float4*)&Ws[k][tc];
            acc[0][0] += ra0 * rb.x; acc[0][1] += ra0 * rb.y;
            acc[0][2] += ra0 * rb.z; acc[0][3] += ra0 * rb.w;
            acc[1][0] += ra1 * rb.x; acc[1][1] += ra1 * rb.y;
            acc[1][2] += ra1 * rb.z; acc[1][3] += ra1 * rb.w;
            acc[2][0] += ra2 * rb.x; acc[2][1] += ra2 * rb.y;
            acc[2][2] += ra2 * rb.z; acc[2][3] += ra2 * rb.w;
            acc[3][0] += ra3 * rb.x; acc[3][1] += ra3 * rb.y;
            acc[3][2] += ra3 * rb.z; acc[3][3] += ra3 * rb.w;
        }
        __syncthreads();
    }

    #pragma unroll
    for (int m = 0; m < 4; m++) {
        int r = row0 + tr + m;
        if (r < nrows)
            *(float4*)(out + (size_t)r * ATTN + tc) =
                make_float4(acc[m][0], acc[m][1], acc[m][2], acc[m][3]);
    }
}

// ---------------- K3: edge weights + count + max -----------------------------
__global__ void edge_weight_kernel(const int* __restrict__ ei,
                                   const float* __restrict__ b1,
                                   const float* __restrict__ W2,
                                   const float* __restrict__ b2,
                                   int n_edges) {
    int e = blockIdx.x * blockDim.x + threadIdx.x;
    bool valid = (e < n_edges);
    float w = 0.f;
    if (valid) {
        int s = ei[e];
        int d = ei[n_edges + e];
        const float4* u4 = (const float4*)(g_U1 + (size_t)s * ATTN);
        const float4* i4 = (const float4*)(g_I1 + (size_t)d * ATTN);
        const float4* b4 = (const float4*)b1;
        const float4* w4 = (const float4*)W2;
        float sum = 0.f;
        #pragma unroll
        for (int q = 0; q < ATTN / 4; q++) {
            float4 a = u4[q], b = i4[q], c = b4[q], v = w4[q];
            float h;
            h = a.x + b.x + c.x; h = (h >= 0.f) ? h : 0.2f * h; sum += h * v.x;
            h = a.y + b.y + c.y; h = (h >= 0.f) ? h : 0.2f * h; sum += h * v.y;
            h = a.z + b.z + c.z; h = (h >= 0.f) ? h : 0.2f * h; sum += h * v.z;
            h = a.w + b.w + c.w; h = (h >= 0.f) ? h : 0.2f * h; sum += h * v.w;
        }
        float z = sum + b2[0];
        w = 1.0f / (1.0f + expf(-z));
        g_w[e] = w;
    }
    unsigned keepmask = __ballot_sync(0xffffffffu, valid && (w > THR));
    unsigned bits     = valid ? __float_as_uint(w) : 0u;
    unsigned mx       = __reduce_max_sync(0xffffffffu, bits);
    if ((threadIdx.x & 31) == 0) {
        if (keepmask) atomicAdd(&g_count, __popc(keepmask));
        atomicMax(&g_maxbits, mx);
    }
}

// ---------------- K4: first index of max (fallback argmax) -------------------
__global__ void argmax_kernel(int n_edges) {
    if (g_count > 0) return;
    int e = blockIdx.x * blockDim.x + threadIdx.x;
    if (e >= n_edges) return;
    if (__float_as_uint(g_w[e]) == g_maxbits) atomicMin(&g_argidx, e);
}

// ---------------- K5: finalize mask, emit edge output, degrees ---------------
__global__ void finalize_kernel(const int* __restrict__ ei,
                                float* __restrict__ out_edge, int n_edges) {
    int e = blockIdx.x * blockDim.x + threadIdx.x;
    if (e >= n_edges) return;
    float w    = g_w[e];
    bool  keep = (g_count > 0) ? (w > THR) : (e == g_argidx);
    out_edge[e] = keep ? w : 0.0f;
    if (keep) atomicAdd(&g_deg[ei[n_edges + e]], 1.0f);
}

// ---------------- K6: split-bf16 HMMA GEMM  xw = X @ W -----------------------
// C = Ahi*Bhi + Ahi*Blo + Alo*Bhi   (3 passes over K=256, bf16, fp32 accum)
#define GBM 128
#define GBN 128
#define GBK 32
#define BKP 40            // padded smem k-stride (bf16): conflict-free frags

__global__ __launch_bounds__(256, 2)
void gemm_bf16_kernel(const float* __restrict__ bias,
                      float* __restrict__ out_gcn, int n_nodes) {
    __shared__ __nv_bfloat16 As[2][GBM * BKP];
    __shared__ __nv_bfloat16 Bs[2][GBN * BKP];

    const int tid  = threadIdx.x;
    const int warp = tid >> 5;
    const int lane = tid & 31;
    const int wr   = warp >> 2;          // 0..1  (64-row warp tiles)
    const int wc   = warp & 3;           // 0..3  (32-col warp tiles)
    const int grp  = lane >> 2;          // 0..7
    const int tq   = lane & 3;           // 0..3
    const int row0 = blockIdx.x * GBM;
    const int col0 = blockIdx.y * GBN;

    const int lr = tid >> 2;             // 0..63
    const int lc = (tid & 3) * 8;        // 0,8,16,24

    float acc[4][4][4];
    #pragma unroll
    for (int mf = 0; mf < 4; mf++)
        #pragma unroll
        for (int nf = 0; nf < 4; nf++)
            #pragma unroll
            for (int c = 0; c < 4; c++) acc[mf][nf][c] = 0.f;

    const int NT = 3 * (HID / GBK);      // 24 tiles

    uint4 ra0, ra1, rb0, rb1;
    auto ldg_tile = [&](int t, uint4& a0, uint4& a1, uint4& b0, uint4& b1) {
        int pass = t >> 3;
        int kk   = (t & 7) * GBK;
        const __nv_bfloat16* Ap = (pass == 2) ? g_Alo : g_Ahi;
        const __nv_bfloat16* Bp = (pass == 1) ? g_Blo : g_Bhi;
        a0 = *(const uint4*)(Ap + (size_t)(row0 + lr)      * HID + kk + lc);
        a1 = *(const uint4*)(Ap + (size_t)(row0 + lr + 64) * HID + kk + lc);
        b0 = *(const uint4*)(Bp + (size_t)(col0 + lr)      * HID + kk + lc);
        b1 = *(const uint4*)(Bp + (size_t)(col0 + lr + 64) * HID + kk + lc);
    };
    auto sts_tile = [&](int buf, uint4 a0, uint4 a1, uint4 b0, uint4 b1) {
        uint2* pa0 = (uint2*)&As[buf][lr * BKP + lc];
        pa0[0] = make_uint2(a0.x, a0.y); pa0[1] = make_uint2(a0.z, a0.w);
        uint2* pa1 = (uint2*)&As[buf][(lr + 64) * BKP + lc];
        pa1[0] = make_uint2(a1.x, a1.y); pa1[1] = make_uint2(a1.z, a1.w);
        uint2* pb0 = (uint2*)&Bs[buf][lr * BKP + lc];
        pb0[0] = make_uint2(b0.x, b0.y); pb0[1] = make_uint2(b0.z, b0.w);
        uint2* pb1 = (uint2*)&Bs[buf][(lr + 64) * BKP + lc];
        pb1[0] = make_uint2(b1.x, b1.y); pb1[1] = make_uint2(b1.z, b1.w);
    };

    ldg_tile(0, ra0, ra1, rb0, rb1);
    sts_tile(0, ra0, ra1, rb0, rb1);
    __syncthreads();

    int cur = 0;
    for (int t = 0; t < NT; t++) {
        bool has_next = (t + 1 < NT);
        if (has_next) ldg_tile(t + 1, ra0, ra1, rb0, rb1);

        #pragma unroll
        for (int ks = 0; ks < 2; ks++) {
            int k0 = ks * 16;
            unsigned afr[4][4], bfr[4][2];
            #pragma unroll
            for (int mf = 0; mf < 4; mf++) {
                const __nv_bfloat16* ab =
                    &As[cur][(wr * 64 + mf * 16 + grp) * BKP + k0 + 2 * tq];
                afr[mf][0] = *(const unsigned*)(ab);
                afr[mf][1] = *(const unsigned*)(ab + 8 * BKP);
                afr[mf][2] = *(const unsigned*)(ab + 8);
                afr[mf][3] = *(const unsigned*)(ab + 8 * BKP + 8);
            }
            #pragma unroll
            for (int nf = 0; nf < 4; nf++) {
                const __nv_bfloat16* bb =
                    &Bs[cur][(wc * 32 + nf * 8 + grp) * BKP + k0 + 2 * tq];
                bfr[nf][0] = *(const unsigned*)(bb);
                bfr[nf][1] = *(const unsigned*)(bb + 8);
            }
            #pragma unroll
            for (int mf = 0; mf < 4; mf++)
                #pragma unroll
                for (int nf = 0; nf < 4; nf++) {
                    float* c = acc[mf][nf];
                    asm volatile(
                        "mma.sync.aligned.m16n8k16.row.col.f32.bf16.bf16.f32 "
                        "{%0,%1,%2,%3}, {%4,%5,%6,%7}, {%8,%9}, {%0,%1,%2,%3};"
                        : "+f"(c[0]), "+f"(c[1]), "+f"(c[2]), "+f"(c[3])
                        : "r"(afr[mf][0]), "r"(afr[mf][1]),
                          "r"(afr[mf][2]), "r"(afr[mf][3]),
                          "r"(bfr[nf][0]), "r"(bfr[nf][1]));
                }
        }

        if (has_next) {
            int nxt = cur ^ 1;
            sts_tile(nxt, ra0, ra1, rb0, rb1);
            __syncthreads();
            cur = nxt;
        }
    }

    #pragma unroll
    for (int mf = 0; mf < 4; mf++) {
        int r1 = row0 + wr * 64 + mf * 16 + grp;
        int r2 = r1 + 8;
        float s1 = (r1 < n_nodes) ? (1.0f / g_deg[r1]) : 0.f;
        float s2 = (r2 < n_nodes) ? (1.0f / g_deg[r2]) : 0.f;
        #pragma unroll
        for (int nf = 0; nf < 4; nf++) {
            int cc = col0 + wc * 32 + nf * 8 + 2 * tq;
            float2 b = *(const float2*)(bias + cc);
            const float* c = acc[mf][nf];
            if (r1 < n_nodes) {
                *(float2*)(g_xw    + (size_t)r1 * HID + cc) = make_float2(c[0], c[1]);
                *(float2*)(out_gcn + (size_t)r1 * HID + cc) =
                    make_float2(c[0] * s1 + b.x, c[1] * s1 + b.y);
            }
            if (r2 < n_nodes) {
                *(float2*)(g_xw    + (size_t)r2 * HID + cc) = make_float2(c[2], c[3]);
                *(float2*)(out_gcn + (size_t)r2 * HID + cc) =
                    make_float2(c[2] * s2 + b.x, c[3] * s2 + b.y);
            }
        }
    }
}

// ---------------- K7: message scatter (one warp per edge, v4 reductions) -----
__global__ void scatter_kernel(const int* __restrict__ ei,
                               const float* __restrict__ out_edge,
                               float* __restrict__ out_gcn, int n_edges) {
    int warp = (blockIdx.x * blockDim.x + threadIdx.x) >> 5;
    int lane = threadIdx.x & 31;
    if (warp >= n_edges) return;
    float wv = out_edge[warp];
    if (wv == 0.0f) return;
    int s = ei[warp];
    int d = ei[n_edges + warp];
    float coef = rsqrtf(g_deg[s]) * rsqrtf(g_deg[d]);
    const float4* xr   = (const float4*)(g_xw + (size_t)s * HID);
    float4*       orow = (float4*)(out_gcn + (size_t)d * HID);
    #pragma unroll
    for (int i = 0; i < HID / 128; i++) {
        float4 v = xr[lane + 32 * i];
        v.x *= coef; v.y *= coef; v.z *= coef; v.w *= coef;
        asm volatile("red.global.add.v4.f32 [%0], {%1, %2, %3, %4};"
                     :: "l"(&orow[lane + 32 * i]),
                        "f"(v.x), "f"(v.y), "f"(v.z), "f"(v.w)
                     : "memory");
    }
}

// ---------------- launch ------------------------------------------------------
extern "C" void kernel_launch(void* const* d_in, const int* in_sizes, int n_in,
                              void* d_out, int out_size) {
    const float* uemb = (const float*)d_in[0];
    const float* iemb = (const float*)d_in[1];
    const int*   ei   = (const int*)d_in[2];
    const float* W1   = (const float*)d_in[3];
    const float* b1   = (const float*)d_in[4];
    const float* W2   = (const float*)d_in[5];
    const float* b2   = (const float*)d_in[6];
    const float* gW   = (const float*)d_in[7];
    const float* gb   = (const float*)d_in[8];

    int n_users = in_sizes[0] / HID;
    int n_items = in_sizes[1] / HID;
    int n_edges = in_sizes[2] / 2;
    int n_nodes = n_users + n_items;

    float* out_gcn  = (float*)d_out;
    float* out_edge = out_gcn + (size_t)n_nodes * HID;

    init_kernel<<<(n_nodes / 4 + 255) / 256, 256>>>(n_nodes);

    convert_x_kernel<<<(MPAD * 32) / 256, 256>>>(uemb, iemb, n_users, n_nodes);
    convert_w_kernel<<<(HID * HID) / 256, 256>>>(gW);

    int ublk = (n_users + ABM - 1) / ABM;
    int iblk = (n_items + ABM - 1) / ABM;
    attn_precompute_kernel<<<ublk + iblk, 256>>>(uemb, iemb, W1,
                                                 n_users, n_items, ublk);

    edge_weight_kernel<<<(n_edges + 255) / 256, 256>>>(ei, b1, W2, b2, n_edges);

    argmax_kernel<<<(n_edges + 255) / 256, 256>>>(n_edges);

    finalize_kernel<<<(n_edges + 255) / 256, 256>>>(ei, out_edge, n_edges);

    dim3 ggrid(MPAD / GBM, HID / GBN);
    gemm_bf16_kernel<<<ggrid, 256>>>(gb, out_gcn, n_nodes);

    scatter_kernel<<<(n_edges * 32 + 255) / 256, 256>>>(ei, out_edge, out_gcn,
                                                        n_edges);
}

// round 11
// speedup vs baseline: 1.6838x; 1.0170x over previous
#include <cuda_runtime.h>
#include <cuda_bf16.h>
#include <math.h>

#define HID   256
#define ATTN  32
#define MAXU  10000
#define MAXI  30000
#define MAXE  500000
#define MAXN  40000
#define MPAD  40960          // 320 * 128, padded M for the GEMM
#define THR   0.8f

// ---------------- scratch (device globals: no allocations allowed) ----------
__device__ float         g_U1[MAXU * ATTN];
__device__ float         g_I1[MAXI * ATTN];
__device__ float         g_w[MAXE];
__device__ float         g_xw[(size_t)MAXN * HID];
__device__ float         g_deg[MAXN];
__device__ int           g_count;
__device__ unsigned      g_maxbits;
__device__ int           g_argidx;
// split-bf16 GEMM operands
__device__ __nv_bfloat16 g_Ahi[(size_t)MPAD * HID];
__device__ __nv_bfloat16 g_Alo[(size_t)MPAD * HID];
__device__ __nv_bfloat16 g_Bhi[HID * HID];   // W^T  [n][k]
__device__ __nv_bfloat16 g_Blo[HID * HID];   // W^T  [n][k]

// ---------------- K0: init + A-pad zero + split-bf16 W transpose -------------
__global__ void setup_kernel(const float* __restrict__ W, int n_nodes) {
    int t = blockIdx.x * blockDim.x + threadIdx.x;   // 65536 threads

    // job 1: degree init (10000 float4 stores)
    if (t * 4 < n_nodes) {
        float4 one = make_float4(1.f, 1.f, 1.f, 1.f);
        *(float4*)&g_deg[t * 4] = one;
    }
    if (t == 0) { g_count = 0; g_maxbits = 0u; g_argidx = 0x7fffffff; }

    // job 2: zero pad rows [MAXN, MPAD) of Ahi/Alo (960 rows * 32 uint4)
    if (t < (MPAD - MAXN) * (HID / 8)) {
        size_t off = (size_t)MAXN * HID + (size_t)t * 8;
        uint4 z = make_uint4(0u, 0u, 0u, 0u);
        *(uint4*)&g_Ahi[off] = z;
        *(uint4*)&g_Alo[off] = z;
    }

    // job 3: split-bf16 transpose of W (65536 elements)
    if (t < HID * HID) {
        int k = t >> 8, n = t & 255;
        float x = W[t];                              // W[k][n], coalesced read
        __nv_bfloat16 h = __float2bfloat16_rn(x);
        __nv_bfloat16 l = __float2bfloat16_rn(x - __bfloat162float(h));
        g_Bhi[n * HID + k] = h;
        g_Blo[n * HID + k] = l;
    }
}

// ---------------- K1: attention projections + fused X bf16-split export ------
// Per block: 128 rows x 32 cols of one node type (uniform W1 half).
// Grid: [0, UBLK) -> user rows, [UBLK, UBLK+IBLK) -> item rows.
// While staging X tiles it also emits g_Ahi/g_Alo (split-bf16 of X).
#define ABM 128
#define ABK 32
#define XPAD 4               // row stride 36 floats = 144 B: 16B-aligned float4s

__global__ __launch_bounds__(256, 3)
void attn_precompute_kernel(const float* __restrict__ uemb,
                            const float* __restrict__ iemb,
                            const float* __restrict__ W1,
                            int n_users, int n_items, int ublk) {
    __shared__ float Xs[ABM][ABK + XPAD];   // 18 KB
    __shared__ float Ws[ABK][ATTN];         // 4 KB

    int b = blockIdx.x;
    const float* X;
    const float* Wb;
    float*       out;
    int          nrows, row0, grow0;
    if (b < ublk) {
        X = uemb; Wb = W1;                      out = g_U1;
        nrows = n_users; row0 = b * ABM; grow0 = row0;
    } else {
        X = iemb; Wb = W1 + (size_t)HID * ATTN; out = g_I1;
        nrows = n_items; row0 = (b - ublk) * ABM; grow0 = n_users + row0;
    }

    int tid = threadIdx.x;
    // X stage map: 2 threads per row, 16 floats each
    int lxr = tid >> 1;            // 0..127
    int lxc = (tid & 1) * 16;      // 0 or 16
    // W stage map: 4 floats per thread
    int lwr = tid >> 3;            // 0..31
    int lwc = (tid & 7) * 4;       // 0..28
    // compute map: 4 rows x 4 cols per thread
    int tr = (tid >> 3) * 4;       // 0..124
    int tc = (tid & 7) * 4;        // 0..28

    float acc[4][4];
    #pragma unroll
    for (int m = 0; m < 4; m++)
        #pragma unroll
        for (int n = 0; n < 4; n++) acc[m][n] = 0.f;

    int xrow = row0 + lxr;
    const float* xp = (xrow < nrows) ? (X + (size_t)xrow * HID) : nullptr;
    size_t aoff0 = (size_t)(grow0 + lxr) * HID + lxc;   // bf16 export base

    for (int kk = 0; kk < HID; kk += ABK) {
        // stage X tile (and export split-bf16 while data is in registers)
        float4 v0 = make_float4(0.f,0.f,0.f,0.f), v1 = v0, v2 = v0, v3 = v0;
        if (xp) {
            v0 = *(const float4*)(xp + kk + lxc);
            v1 = *(const float4*)(xp + kk + lxc + 4);
            v2 = *(const float4*)(xp + kk + lxc + 8);
            v3 = *(const float4*)(xp + kk + lxc + 12);
        }
        *(float4*)&Xs[lxr][lxc]      = v0;
        *(float4*)&Xs[lxr][lxc + 4]  = v1;
        *(float4*)&Xs[lxr][lxc + 8]  = v2;
        *(float4*)&Xs[lxr][lxc + 12] = v3;

        if (xp) {
            float f[16];
            f[0]=v0.x; f[1]=v0.y; f[2]=v0.z; f[3]=v0.w;
            f[4]=v1.x; f[5]=v1.y; f[6]=v1.z; f[7]=v1.w;
            f[8]=v2.x; f[9]=v2.y; f[10]=v2.z; f[11]=v2.w;
            f[12]=v3.x; f[13]=v3.y; f[14]=v3.z; f[15]=v3.w;
            unsigned hip[8], lop[8];
            #pragma unroll
            for (int i = 0; i < 8; i++) {
                __nv_bfloat162 h = __floats2bfloat162_rn(f[2*i], f[2*i+1]);
                hip[i] = *(unsigned*)&h;
                __nv_bfloat162 l = __floats2bfloat162_rn(
                    f[2*i]   - __bfloat162float(__low2bfloat16(h)),
                    f[2*i+1] - __bfloat162float(__high2bfloat16(h)));
                lop[i] = *(unsigned*)&l;
            }
            size_t off = aoff0 + kk;
            *(uint4*)&g_Ahi[off]     = make_uint4(hip[0], hip[1], hip[2], hip[3]);
            *(uint4*)&g_Ahi[off + 8] = make_uint4(hip[4], hip[5], hip[6], hip[7]);
            *(uint4*)&g_Alo[off]     = make_uint4(lop[0], lop[1], lop[2], lop[3]);
            *(uint4*)&g_Alo[off + 8] = make_uint4(lop[4], lop[5], lop[6], lop[7]);
        }

        // stage W chunk
        *(float4*)&Ws[lwr][lwc] =
            *(const float4*)(Wb + (size_t)(kk + lwr) * ATTN + lwc);
        __syncthreads();

        // vectorized compute: 4 k per step, float4 reads of Xs and Ws
        #pragma unroll
        for (int k4 = 0; k4 < ABK; k4 += 4) {
            float4 xa0 = *(const float4*)&Xs[tr + 0][k4];
            float4 xa1 = *(const float4*)&Xs[tr + 1][k4];
            float4 xa2 = *(const float4*)&Xs[tr + 2][k4];
            float4 xa3 = *(const float4*)&Xs[tr + 3][k4];
            float4 w0  = *(const float4*)&Ws[k4 + 0][tc];
            float4 w1  = *(const float4*)&Ws[k4 + 1][tc];
            float4 w2  = *(const float4*)&Ws[k4 + 2][tc];
            float4 w3  = *(const float4*)&Ws[k4 + 3][tc];
            #pragma unroll
            for (int m = 0; m < 4; m++) {
                float4 xm = (m == 0) ? xa0 : (m == 1) ? xa1 : (m == 2) ? xa2 : xa3;
                acc[m][0] += xm.x * w0.x + xm.y * w1.x + xm.z * w2.x + xm.w * w3.x;
                acc[m][1] += xm.x * w0.y + xm.y * w1.y + xm.z * w2.y + xm.w * w3.y;
                acc[m][2] += xm.x * w0.z + xm.y * w1.z + xm.z * w2.z + xm.w * w3.z;
                acc[m][3] += xm.x * w0.w + xm.y * w1.w + xm.z * w2.w + xm.w * w3.w;
            }
        }
        __syncthreads();
    }

    #pragma unroll
    for (int m = 0; m < 4; m++) {
        int r = row0 + tr + m;
        if (r < nrows)
            *(float4*)(out + (size_t)r * ATTN + tc) =
                make_float4(acc[m][0], acc[m][1], acc[m][2], acc[m][3]);
    }
}

// ---------------- K2: edge weights + count + max -----------------------------
__global__ void edge_weight_kernel(const int* __restrict__ ei,
                                   const float* __restrict__ b1,
                                   const float* __restrict__ W2,
                                   const float* __restrict__ b2,
                                   int n_edges) {
    int e = blockIdx.x * blockDim.x + threadIdx.x;
    bool valid = (e < n_edges);
    float w = 0.f;
    if (valid) {
        int s = ei[e];
        int d = ei[n_edges + e];
        const float4* u4 = (const float4*)(g_U1 + (size_t)s * ATTN);
        const float4* i4 = (const float4*)(g_I1 + (size_t)d * ATTN);
        const float4* b4 = (const float4*)b1;
        const float4* w4 = (const float4*)W2;
        float sum = 0.f;
        #pragma unroll
        for (int q = 0; q < ATTN / 4; q++) {
            float4 a = u4[q], b = i4[q], c = b4[q], v = w4[q];
            float h;
            h = a.x + b.x + c.x; h = (h >= 0.f) ? h : 0.2f * h; sum += h * v.x;
            h = a.y + b.y + c.y; h = (h >= 0.f) ? h : 0.2f * h; sum += h * v.y;
            h = a.z + b.z + c.z; h = (h >= 0.f) ? h : 0.2f * h; sum += h * v.z;
            h = a.w + b.w + c.w; h = (h >= 0.f) ? h : 0.2f * h; sum += h * v.w;
        }
        float z = sum + b2[0];
        w = 1.0f / (1.0f + expf(-z));
        g_w[e] = w;
    }
    unsigned keepmask = __ballot_sync(0xffffffffu, valid && (w > THR));
    unsigned bits     = valid ? __float_as_uint(w) : 0u;
    unsigned mx       = __reduce_max_sync(0xffffffffu, bits);
    if ((threadIdx.x & 31) == 0) {
        if (keepmask) atomicAdd(&g_count, __popc(keepmask));
        atomicMax(&g_maxbits, mx);
    }
}

// ---------------- K3: first index of max (fallback argmax) -------------------
__global__ void argmax_kernel(int n_edges) {
    if (g_count > 0) return;
    int e = blockIdx.x * blockDim.x + threadIdx.x;
    if (e >= n_edges) return;
    if (__float_as_uint(g_w[e]) == g_maxbits) atomicMin(&g_argidx, e);
}

// ---------------- K4: finalize mask, emit edge output, degrees ---------------
__global__ void finalize_kernel(const int* __restrict__ ei,
                                float* __restrict__ out_edge, int n_edges) {
    int e = blockIdx.x * blockDim.x + threadIdx.x;
    if (e >= n_edges) return;
    float w    = g_w[e];
    bool  keep = (g_count > 0) ? (w > THR) : (e == g_argidx);
    out_edge[e] = keep ? w : 0.0f;
    if (keep) atomicAdd(&g_deg[ei[n_edges + e]], 1.0f);
}

// ---------------- K5: split-bf16 HMMA GEMM  xw = X @ W -----------------------
// C = Ahi*Bhi + Ahi*Blo + Alo*Bhi   (3 passes over K=256, bf16, fp32 accum)
#define GBM 128
#define GBN 128
#define GBK 32
#define BKP 40            // padded smem k-stride (bf16): conflict-free frags

__global__ __launch_bounds__(256, 2)
void gemm_bf16_kernel(const float* __restrict__ bias,
                      float* __restrict__ out_gcn, int n_nodes) {
    __shared__ __nv_bfloat16 As[2][GBM * BKP];
    __shared__ __nv_bfloat16 Bs[2][GBN * BKP];

    const int tid  = threadIdx.x;
    const int warp = tid >> 5;
    const int lane = tid & 31;
    const int wr   = warp >> 2;          // 0..1  (64-row warp tiles)
    const int wc   = warp & 3;           // 0..3  (32-col warp tiles)
    const int grp  = lane >> 2;          // 0..7
    const int tq   = lane & 3;           // 0..3
    const int row0 = blockIdx.x * GBM;
    const int col0 = blockIdx.y * GBN;

    const int lr = tid >> 2;             // 0..63
    const int lc = (tid & 3) * 8;        // 0,8,16,24

    float acc[4][4][4];
    #pragma unroll
    for (int mf = 0; mf < 4; mf++)
        #pragma unroll
        for (int nf = 0; nf < 4; nf++)
            #pragma unroll
            for (int c = 0; c < 4; c++) acc[mf][nf][c] = 0.f;

    const int NT = 3 * (HID / GBK);      // 24 tiles

    uint4 ra0, ra1, rb0, rb1;
    auto ldg_tile = [&](int t, uint4& a0, uint4& a1, uint4& b0, uint4& b1) {
        int pass = t >> 3;
        int kk   = (t & 7) * GBK;
        const __nv_bfloat16* Ap = (pass == 2) ? g_Alo : g_Ahi;
        const __nv_bfloat16* Bp = (pass == 1) ? g_Blo : g_Bhi;
        a0 = *(const uint4*)(Ap + (size_t)(row0 + lr)      * HID + kk + lc);
        a1 = *(const uint4*)(Ap + (size_t)(row0 + lr + 64) * HID + kk + lc);
        b0 = *(const uint4*)(Bp + (size_t)(col0 + lr)      * HID + kk + lc);
        b1 = *(const uint4*)(Bp + (size_t)(col0 + lr + 64) * HID + kk + lc);
    };
    auto sts_tile = [&](int buf, uint4 a0, uint4 a1, uint4 b0, uint4 b1) {
        uint2* pa0 = (uint2*)&As[buf][lr * BKP + lc];
        pa0[0] = make_uint2(a0.x, a0.y); pa0[1] = make_uint2(a0.z, a0.w);
        uint2* pa1 = (uint2*)&As[buf][(lr + 64) * BKP + lc];
        pa1[0] = make_uint2(a1.x, a1.y); pa1[1] = make_uint2(a1.z, a1.w);
        uint2* pb0 = (uint2*)&Bs[buf][lr * BKP + lc];
        pb0[0] = make_uint2(b0.x, b0.y); pb0[1] = make_uint2(b0.z, b0.w);
        uint2* pb1 = (uint2*)&Bs[buf][(lr + 64) * BKP + lc];
        pb1[0] = make_uint2(b1.x, b1.y); pb1[1] = make_uint2(b1.z, b1.w);
    };

    ldg_tile(0, ra0, ra1, rb0, rb1);
    sts_tile(0, ra0, ra1, rb0, rb1);
    __syncthreads();

    int cur = 0;
    for (int t = 0; t < NT; t++) {
        bool has_next = (t + 1 < NT);
        if (has_next) ldg_tile(t + 1, ra0, ra1, rb0, rb1);

        #pragma unroll
        for (int ks = 0; ks < 2; ks++) {
            int k0 = ks * 16;
            unsigned afr[4][4], bfr[4][2];
            #pragma unroll
            for (int mf = 0; mf < 4; mf++) {
                const __nv_bfloat16* ab =
                    &As[cur][(wr * 64 + mf * 16 + grp) * BKP + k0 + 2 * tq];
                afr[mf][0] = *(const unsigned*)(ab);
                afr[mf][1] = *(const unsigned*)(ab + 8 * BKP);
                afr[mf][2] = *(const unsigned*)(ab + 8);
                afr[mf][3] = *(const unsigned*)(ab + 8 * BKP + 8);
            }
            #pragma unroll
            for (int nf = 0; nf < 4; nf++) {
                const __nv_bfloat16* bb =
                    &Bs[cur][(wc * 32 + nf * 8 + grp) * BKP + k0 + 2 * tq];
                bfr[nf][0] = *(const unsigned*)(bb);
                bfr[nf][1] = *(const unsigned*)(bb + 8);
            }
            #pragma unroll
            for (int mf = 0; mf < 4; mf++)
                #pragma unroll
                for (int nf = 0; nf < 4; nf++) {
                    float* c = acc[mf][nf];
                    asm volatile(
                        "mma.sync.aligned.m16n8k16.row.col.f32.bf16.bf16.f32 "
                        "{%0,%1,%2,%3}, {%4,%5,%6,%7}, {%8,%9}, {%0,%1,%2,%3};"
                        : "+f"(c[0]), "+f"(c[1]), "+f"(c[2]), "+f"(c[3])
                        : "r"(afr[mf][0]), "r"(afr[mf][1]),
                          "r"(afr[mf][2]), "r"(afr[mf][3]),
                          "r"(bfr[nf][0]), "r"(bfr[nf][1]));
                }
        }

        if (has_next) {
            int nxt = cur ^ 1;
            sts_tile(nxt, ra0, ra1, rb0, rb1);
            __syncthreads();
            cur = nxt;
        }
    }

    #pragma unroll
    for (int mf = 0; mf < 4; mf++) {
        int r1 = row0 + wr * 64 + mf * 16 + grp;
        int r2 = r1 + 8;
        float s1 = (r1 < n_nodes) ? (1.0f / g_deg[r1]) : 0.f;
        float s2 = (r2 < n_nodes) ? (1.0f / g_deg[r2]) : 0.f;
        #pragma unroll
        for (int nf = 0; nf < 4; nf++) {
            int cc = col0 + wc * 32 + nf * 8 + 2 * tq;
            float2 b = *(const float2*)(bias + cc);
            const float* c = acc[mf][nf];
            if (r1 < n_nodes) {
                *(float2*)(g_xw    + (size_t)r1 * HID + cc) = make_float2(c[0], c[1]);
                *(float2*)(out_gcn + (size_t)r1 * HID + cc) =
                    make_float2(c[0] * s1 + b.x, c[1] * s1 + b.y);
            }
            if (r2 < n_nodes) {
                *(float2*)(g_xw    + (size_t)r2 * HID + cc) = make_float2(c[2], c[3]);
                *(float2*)(out_gcn + (size_t)r2 * HID + cc) =
                    make_float2(c[2] * s2 + b.x, c[3] * s2 + b.y);
            }
        }
    }
}

// ---------------- K6: message scatter (one warp per edge, v4 reductions) -----
__global__ void scatter_kernel(const int* __restrict__ ei,
                               const float* __restrict__ out_edge,
                               float* __restrict__ out_gcn, int n_edges) {
    int warp = (blockIdx.x * blockDim.x + threadIdx.x) >> 5;
    int lane = threadIdx.x & 31;
    if (warp >= n_edges) return;
    float wv = out_edge[warp];
    if (wv == 0.0f) return;
    int s = ei[warp];
    int d = ei[n_edges + warp];
    float coef = rsqrtf(g_deg[s]) * rsqrtf(g_deg[d]);
    const float4* xr   = (const float4*)(g_xw + (size_t)s * HID);
    float4*       orow = (float4*)(out_gcn + (size_t)d * HID);
    #pragma unroll
    for (int i = 0; i < HID / 128; i++) {
        float4 v = xr[lane + 32 * i];
        v.x *= coef; v.y *= coef; v.z *= coef; v.w *= coef;
        asm volatile("red.global.add.v4.f32 [%0], {%1, %2, %3, %4};"
                     :: "l"(&orow[lane + 32 * i]),
                        "f"(v.x), "f"(v.y), "f"(v.z), "f"(v.w)
                     : "memory");
    }
}

// ---------------- launch ------------------------------------------------------
extern "C" void kernel_launch(void* const* d_in, const int* in_sizes, int n_in,
                              void* d_out, int out_size) {
    const float* uemb = (const float*)d_in[0];
    const float* iemb = (const float*)d_in[1];
    const int*   ei   = (const int*)d_in[2];
    const float* W1   = (const float*)d_in[3];
    const float* b1   = (const float*)d_in[4];
    const float* W2   = (const float*)d_in[5];
    const float* b2   = (const float*)d_in[6];
    const float* gW   = (const float*)d_in[7];
    const float* gb   = (const float*)d_in[8];

    int n_users = in_sizes[0] / HID;
    int n_items = in_sizes[1] / HID;
    int n_edges = in_sizes[2] / 2;
    int n_nodes = n_users + n_items;

    float* out_gcn  = (float*)d_out;
    float* out_edge = out_gcn + (size_t)n_nodes * HID;

    setup_kernel<<<(HID * HID) / 256, 256>>>(gW, n_nodes);

    int ublk = (n_users + ABM - 1) / ABM;
    int iblk = (n_items + ABM - 1) / ABM;
    attn_precompute_kernel<<<ublk + iblk, 256>>>(uemb, iemb, W1,
                                                 n_users, n_items, ublk);

    edge_weight_kernel<<<(n_edges + 255) / 256, 256>>>(ei, b1, W2, b2, n_edges);

    argmax_kernel<<<(n_edges + 255) / 256, 256>>>(n_edges);

    finalize_kernel<<<(n_edges + 255) / 256, 256>>>(ei, out_edge, n_edges);

    dim3 ggrid(MPAD / GBM, HID / GBN);
    gemm_bf16_kernel<<<ggrid, 256>>>(gb, out_gcn, n_nodes);

    scatter_kernel<<<(n_edges * 32 + 255) / 256, 256>>>(ei, out_edge, out_gcn,
                                                        n_edges);
}

// round 15
// speedup vs baseline: 1.9759x; 1.1735x over previous
#include <cuda_runtime.h>
#include <cuda_bf16.h>
#include <math.h>

#define HID   256
#define ATTN  32
#define MAXU  10000
#define MAXI  30000
#define MAXE  500000
#define MAXN  40000
#define MPAD  40960          // 320 * 128, padded M for the GEMM
#define THR   0.8f

// ---------------- scratch (device globals: no allocations allowed) ----------
__device__ float         g_U1[MAXU * ATTN];
__device__ float         g_I1[MAXI * ATTN];
__device__ float         g_w[MAXE];
__device__ float         g_xw[(size_t)MAXN * HID];
__device__ float         g_deg[MAXN];
__device__ int           g_count;
__device__ unsigned      g_maxbits;
__device__ int           g_argidx;
// split-bf16 GEMM operands
__device__ __nv_bfloat16 g_Ahi[(size_t)MPAD * HID];
__device__ __nv_bfloat16 g_Alo[(size_t)MPAD * HID];
__device__ __nv_bfloat16 g_Bhi[HID * HID];   // W^T  [n][k]
__device__ __nv_bfloat16 g_Blo[HID * HID];   // W^T  [n][k]

// ---------------- K0: init + A-pad zero + split-bf16 W transpose -------------
__global__ void setup_kernel(const float* __restrict__ W, int n_nodes) {
    int t = blockIdx.x * blockDim.x + threadIdx.x;   // 65536 threads

    if (t * 4 < n_nodes) {
        float4 one = make_float4(1.f, 1.f, 1.f, 1.f);
        *(float4*)&g_deg[t * 4] = one;
    }
    if (t == 0) { g_count = 0; g_maxbits = 0u; g_argidx = 0x7fffffff; }

    if (t < (MPAD - MAXN) * (HID / 8)) {
        size_t off = (size_t)MAXN * HID + (size_t)t * 8;
        uint4 z = make_uint4(0u, 0u, 0u, 0u);
        *(uint4*)&g_Ahi[off] = z;
        *(uint4*)&g_Alo[off] = z;
    }

    if (t < HID * HID) {
        int k = t >> 8, n = t & 255;
        float x = W[t];                              // W[k][n], coalesced read
        __nv_bfloat16 h = __float2bfloat16_rn(x);
        __nv_bfloat16 l = __float2bfloat16_rn(x - __bfloat162float(h));
        g_Bhi[n * HID + k] = h;
        g_Blo[n * HID + k] = l;
    }
}

// ---------------- K1: attention projections + fused X bf16-split export ------
#define ABM 128
#define ABK 32
#define XPAD 4               // row stride 36 floats = 144 B: 16B-aligned float4s

__global__ __launch_bounds__(256, 3)
void attn_precompute_kernel(const float* __restrict__ uemb,
                            const float* __restrict__ iemb,
                            const float* __restrict__ W1,
                            int n_users, int n_items, int ublk) {
    __shared__ float Xs[ABM][ABK + XPAD];   // 18 KB
    __shared__ float Ws[ABK][ATTN];         // 4 KB

    int b = blockIdx.x;
    const float* X;
    const float* Wb;
    float*       out;
    int          nrows, row0, grow0;
    if (b < ublk) {
        X = uemb; Wb = W1;                      out = g_U1;
        nrows = n_users; row0 = b * ABM; grow0 = row0;
    } else {
        X = iemb; Wb = W1 + (size_t)HID * ATTN; out = g_I1;
        nrows = n_items; row0 = (b - ublk) * ABM; grow0 = n_users + row0;
    }

    int tid = threadIdx.x;
    int lxr = tid >> 1;            // 0..127
    int lxc = (tid & 1) * 16;      // 0 or 16
    int lwr = tid >> 3;            // 0..31
    int lwc = (tid & 7) * 4;       // 0..28
    int tr = (tid >> 3) * 4;       // 0..124
    int tc = (tid & 7) * 4;        // 0..28

    float acc[4][4];
    #pragma unroll
    for (int m = 0; m < 4; m++)
        #pragma unroll
        for (int n = 0; n < 4; n++) acc[m][n] = 0.f;

    int xrow = row0 + lxr;
    const float* xp = (xrow < nrows) ? (X + (size_t)xrow * HID) : nullptr;
    size_t aoff0 = (size_t)(grow0 + lxr) * HID + lxc;

    for (int kk = 0; kk < HID; kk += ABK) {
        float4 v0 = make_float4(0.f,0.f,0.f,0.f), v1 = v0, v2 = v0, v3 = v0;
        if (xp) {
            v0 = *(const float4*)(xp + kk + lxc);
            v1 = *(const float4*)(xp + kk + lxc + 4);
            v2 = *(const float4*)(xp + kk + lxc + 8);
            v3 = *(const float4*)(xp + kk + lxc + 12);
        }
        *(float4*)&Xs[lxr][lxc]      = v0;
        *(float4*)&Xs[lxr][lxc + 4]  = v1;
        *(float4*)&Xs[lxr][lxc + 8]  = v2;
        *(float4*)&Xs[lxr][lxc + 12] = v3;

        if (xp) {
            float f[16];
            f[0]=v0.x; f[1]=v0.y; f[2]=v0.z; f[3]=v0.w;
            f[4]=v1.x; f[5]=v1.y; f[6]=v1.z; f[7]=v1.w;
            f[8]=v2.x; f[9]=v2.y; f[10]=v2.z; f[11]=v2.w;
            f[12]=v3.x; f[13]=v3.y; f[14]=v3.z; f[15]=v3.w;
            unsigned hip[8], lop[8];
            #pragma unroll
            for (int i = 0; i < 8; i++) {
                __nv_bfloat162 h = __floats2bfloat162_rn(f[2*i], f[2*i+1]);
                hip[i] = *(unsigned*)&h;
                __nv_bfloat162 l = __floats2bfloat162_rn(
                    f[2*i]   - __bfloat162float(__low2bfloat16(h)),
                    f[2*i+1] - __bfloat162float(__high2bfloat16(h)));
                lop[i] = *(unsigned*)&l;
            }
            size_t off = aoff0 + kk;
            *(uint4*)&g_Ahi[off]     = make_uint4(hip[0], hip[1], hip[2], hip[3]);
            *(uint4*)&g_Ahi[off + 8] = make_uint4(hip[4], hip[5], hip[6], hip[7]);
            *(uint4*)&g_Alo[off]     = make_uint4(lop[0], lop[1], lop[2], lop[3]);
            *(uint4*)&g_Alo[off + 8] = make_uint4(lop[4], lop[5], lop[6], lop[7]);
        }

        *(float4*)&Ws[lwr][lwc] =
            *(const float4*)(Wb + (size_t)(kk + lwr) * ATTN + lwc);
        __syncthreads();

        #pragma unroll
        for (int k4 = 0; k4 < ABK; k4 += 4) {
            float4 xa0 = *(const float4*)&Xs[tr + 0][k4];
            float4 xa1 = *(const float4*)&Xs[tr + 1][k4];
            float4 xa2 = *(const float4*)&Xs[tr + 2][k4];
            float4 xa3 = *(const float4*)&Xs[tr + 3][k4];
            float4 w0  = *(const float4*)&Ws[k4 + 0][tc];
            float4 w1  = *(const float4*)&Ws[k4 + 1][tc];
            float4 w2  = *(const float4*)&Ws[k4 + 2][tc];
            float4 w3  = *(const float4*)&Ws[k4 + 3][tc];
            #pragma unroll
            for (int m = 0; m < 4; m++) {
                float4 xm = (m == 0) ? xa0 : (m == 1) ? xa1 : (m == 2) ? xa2 : xa3;
                acc[m][0] += xm.x * w0.x + xm.y * w1.x + xm.z * w2.x + xm.w * w3.x;
                acc[m][1] += xm.x * w0.y + xm.y * w1.y + xm.z * w2.y + xm.w * w3.y;
                acc[m][2] += xm.x * w0.z + xm.y * w1.z + xm.z * w2.z + xm.w * w3.z;
                acc[m][3] += xm.x * w0.w + xm.y * w1.w + xm.z * w2.w + xm.w * w3.w;
            }
        }
        __syncthreads();
    }

    #pragma unroll
    for (int m = 0; m < 4; m++) {
        int r = row0 + tr + m;
        if (r < nrows)
            *(float4*)(out + (size_t)r * ATTN + tc) =
                make_float4(acc[m][0], acc[m][1], acc[m][2], acc[m][3]);
    }
}

// ---------------- K2: edge weights + count + max -----------------------------
__global__ void edge_weight_kernel(const int* __restrict__ ei,
                                   const float* __restrict__ b1,
                                   const float* __restrict__ W2,
                                   const float* __restrict__ b2,
                                   int n_edges) {
    int e = blockIdx.x * blockDim.x + threadIdx.x;
    bool valid = (e < n_edges);
    float w = 0.f;
    if (valid) {
        int s = ei[e];
        int d = ei[n_edges + e];
        const float4* u4 = (const float4*)(g_U1 + (size_t)s * ATTN);
        const float4* i4 = (const float4*)(g_I1 + (size_t)d * ATTN);
        const float4* b4 = (const float4*)b1;
        const float4* w4 = (const float4*)W2;
        float sum = 0.f;
        #pragma unroll
        for (int q = 0; q < ATTN / 4; q++) {
            float4 a = u4[q], b = i4[q], c = b4[q], v = w4[q];
            float h;
            h = a.x + b.x + c.x; h = (h >= 0.f) ? h : 0.2f * h; sum += h * v.x;
            h = a.y + b.y + c.y; h = (h >= 0.f) ? h : 0.2f * h; sum += h * v.y;
            h = a.z + b.z + c.z; h = (h >= 0.f) ? h : 0.2f * h; sum += h * v.z;
            h = a.w + b.w + c.w; h = (h >= 0.f) ? h : 0.2f * h; sum += h * v.w;
        }
        float z = sum + b2[0];
        w = 1.0f / (1.0f + expf(-z));
        g_w[e] = w;
    }
    unsigned keepmask = __ballot_sync(0xffffffffu, valid && (w > THR));
    unsigned bits     = valid ? __float_as_uint(w) : 0u;
    unsigned mx       = __reduce_max_sync(0xffffffffu, bits);
    if ((threadIdx.x & 31) == 0) {
        if (keepmask) atomicAdd(&g_count, __popc(keepmask));
        atomicMax(&g_maxbits, mx);
    }
}

// ---------------- K3: first index of max (fallback argmax) -------------------
__global__ void argmax_kernel(int n_edges) {
    if (g_count > 0) return;
    int e = blockIdx.x * blockDim.x + threadIdx.x;
    if (e >= n_edges) return;
    if (__float_as_uint(g_w[e]) == g_maxbits) atomicMin(&g_argidx, e);
}

// ---------------- K4: finalize mask, emit edge output, degrees ---------------
__global__ void finalize_kernel(const int* __restrict__ ei,
                                float* __restrict__ out_edge, int n_edges) {
    int e = blockIdx.x * blockDim.x + threadIdx.x;
    if (e >= n_edges) return;
    float w    = g_w[e];
    bool  keep = (g_count > 0) ? (w > THR) : (e == g_argidx);
    out_edge[e] = keep ? w : 0.0f;
    if (keep) atomicAdd(&g_deg[ei[n_edges + e]], 1.0f);
}

// ---------------- K5: split-bf16 HMMA GEMM (double-buffered 3-pass) ----------
// C = Ahi*Bhi + Ahi*Blo + Alo*Bhi   (3 passes over K=256, bf16, fp32 accum)
#define GBM 128
#define GBN 128
#define GBK 32
#define BKP 40            // padded smem k-stride (bf16): conflict-free frags

__global__ __launch_bounds__(256, 2)
void gemm_bf16_kernel(const float* __restrict__ bias,
                      float* __restrict__ out_gcn, int n_nodes) {
    __shared__ __nv_bfloat16 As[2][GBM * BKP];
    __shared__ __nv_bfloat16 Bs[2][GBN * BKP];

    const int tid  = threadIdx.x;
    const int warp = tid >> 5;
    const int lane = tid & 31;
    const int wr   = warp >> 2;          // 0..1
    const int wc   = warp & 3;           // 0..3
    const int grp  = lane >> 2;          // 0..7
    const int tq   = lane & 3;           // 0..3
    const int row0 = blockIdx.x * GBM;
    const int col0 = blockIdx.y * GBN;

    const int lr = tid >> 2;             // 0..63
    const int lc = (tid & 3) * 8;        // 0,8,16,24

    float acc[4][4][4];
    #pragma unroll
    for (int mf = 0; mf < 4; mf++)
        #pragma unroll
        for (int nf = 0; nf < 4; nf++)
            #pragma unroll
            for (int c = 0; c < 4; c++) acc[mf][nf][c] = 0.f;

    const int NT = 3 * (HID / GBK);      // 24 tiles

    uint4 ra0, ra1, rb0, rb1;
    auto ldg_tile = [&](int t, uint4& a0, uint4& a1, uint4& b0, uint4& b1) {
        int pass = t >> 3;
        int kk   = (t & 7) * GBK;
        const __nv_bfloat16* Ap = (pass == 2) ? g_Alo : g_Ahi;
        const __nv_bfloat16* Bp = (pass == 1) ? g_Blo : g_Bhi;
        a0 = *(const uint4*)(Ap + (size_t)(row0 + lr)      * HID + kk + lc);
        a1 = *(const uint4*)(Ap + (size_t)(row0 + lr + 64) * HID + kk + lc);
        b0 = *(const uint4*)(Bp + (size_t)(col0 + lr)      * HID + kk + lc);
        b1 = *(const uint4*)(Bp + (size_t)(col0 + lr + 64) * HID + kk + lc);
    };
    auto sts_tile = [&](int buf, uint4 a0, uint4 a1, uint4 b0, uint4 b1) {
        uint2* pa0 = (uint2*)&As[buf][lr * BKP + lc];
        pa0[0] = make_uint2(a0.x, a0.y); pa0[1] = make_uint2(a0.z, a0.w);
        uint2* pa1 = (uint2*)&As[buf][(lr + 64) * BKP + lc];
        pa1[0] = make_uint2(a1.x, a1.y); pa1[1] = make_uint2(a1.z, a1.w);
        uint2* pb0 = (uint2*)&Bs[buf][lr * BKP + lc];
        pb0[0] = make_uint2(b0.x, b0.y); pb0[1] = make_uint2(b0.z, b0.w);
        uint2* pb1 = (uint2*)&Bs[buf][(lr + 64) * BKP + lc];
        pb1[0] = make_uint2(b1.x, b1.y); pb1[1] = make_uint2(b1.z, b1.w);
    };

    ldg_tile(0, ra0, ra1, rb0, rb1);
    sts_tile(0, ra0, ra1, rb0, rb1);
    __syncthreads();

    int cur = 0;
    for (int t = 0; t < NT; t++) {
        bool has_next = (t + 1 < NT);
        if (has_next) ldg_tile(t + 1, ra0, ra1, rb0, rb1);

        #pragma unroll
        for (int ks = 0; ks < 2; ks++) {
            int k0 = ks * 16;
            unsigned afr[4][4], bfr[4][2];
            #pragma unroll
            for (int mf = 0; mf < 4; mf++) {
                const __nv_bfloat16* ab =
                    &As[cur][(wr * 64 + mf * 16 + grp) * BKP + k0 + 2 * tq];
                afr[mf][0] = *(const unsigned*)(ab);
                afr[mf][1] = *(const unsigned*)(ab + 8 * BKP);
                afr[mf][2] = *(const unsigned*)(ab + 8);
                afr[mf][3] = *(const unsigned*)(ab + 8 * BKP + 8);
            }
            #pragma unroll
            for (int nf = 0; nf < 4; nf++) {
                const __nv_bfloat16* bb =
                    &Bs[cur][(wc * 32 + nf * 8 + grp) * BKP + k0 + 2 * tq];
                bfr[nf][0] = *(const unsigned*)(bb);
                bfr[nf][1] = *(const unsigned*)(bb + 8);
            }
            #pragma unroll
            for (int mf = 0; mf < 4; mf++)
                #pragma unroll
                for (int nf = 0; nf < 4; nf++) {
                    float* c = acc[mf][nf];
                    asm volatile(
                        "mma.sync.aligned.m16n8k16.row.col.f32.bf16.bf16.f32 "
                        "{%0,%1,%2,%3}, {%4,%5,%6,%7}, {%8,%9}, {%0,%1,%2,%3};"
                        : "+f"(c[0]), "+f"(c[1]), "+f"(c[2]), "+f"(c[3])
                        : "r"(afr[mf][0]), "r"(afr[mf][1]),
                          "r"(afr[mf][2]), "r"(afr[mf][3]),
                          "r"(bfr[nf][0]), "r"(bfr[nf][1]));
                }
        }

        if (has_next) {
            int nxt = cur ^ 1;
            sts_tile(nxt, ra0, ra1, rb0, rb1);
            __syncthreads();
            cur = nxt;
        }
    }

    #pragma unroll
    for (int mf = 0; mf < 4; mf++) {
        int r1 = row0 + wr * 64 + mf * 16 + grp;
        int r2 = r1 + 8;
        float s1 = (r1 < n_nodes) ? (1.0f / g_deg[r1]) : 0.f;
        float s2 = (r2 < n_nodes) ? (1.0f / g_deg[r2]) : 0.f;
        #pragma unroll
        for (int nf = 0; nf < 4; nf++) {
            int cc = col0 + wc * 32 + nf * 8 + 2 * tq;
            float2 b = *(const float2*)(bias + cc);
            const float* c = acc[mf][nf];
            if (r1 < n_nodes) {
                *(float2*)(g_xw    + (size_t)r1 * HID + cc) = make_float2(c[0], c[1]);
                *(float2*)(out_gcn + (size_t)r1 * HID + cc) =
                    make_float2(c[0] * s1 + b.x, c[1] * s1 + b.y);
            }
            if (r2 < n_nodes) {
                *(float2*)(g_xw    + (size_t)r2 * HID + cc) = make_float2(c[2], c[3]);
                *(float2*)(out_gcn + (size_t)r2 * HID + cc) =
                    make_float2(c[2] * s2 + b.x, c[3] * s2 + b.y);
            }
        }
    }
}

// ---------------- K6: ballot-scan scatter (no compaction buffer) -------------
// Each warp grid-strides over 32-edge chunks: one coalesced out_edge load +
// ballot selects kept edges; warp processes them cooperatively.
__global__ void scatter_kernel(const int* __restrict__ ei,
                               const float* __restrict__ out_edge,
                               float* __restrict__ out_gcn, int n_edges) {
    int gw     = (blockIdx.x * blockDim.x + threadIdx.x) >> 5;
    int lane   = threadIdx.x & 31;
    int nw     = (gridDim.x * blockDim.x) >> 5;
    int nchunk = (n_edges + 31) >> 5;

    for (int chunk = gw; chunk < nchunk; chunk += nw) {
        int e0 = chunk << 5;
        int e  = e0 + lane;
        float w = (e < n_edges) ? out_edge[e] : 0.f;
        unsigned m = __ballot_sync(0xffffffffu, w != 0.f);
        while (m) {
            int b = __ffs(m) - 1;
            m &= m - 1;
            int ee = e0 + b;
            int s = ei[ee];
            int d = ei[n_edges + ee];
            float coef = rsqrtf(g_deg[s]) * rsqrtf(g_deg[d]);
            const float4* xr   = (const float4*)(g_xw + (size_t)s * HID);
            float4*       orow = (float4*)(out_gcn + (size_t)d * HID);
            #pragma unroll
            for (int j = 0; j < HID / 128; j++) {
                float4 v = xr[lane + 32 * j];
                v.x *= coef; v.y *= coef; v.z *= coef; v.w *= coef;
                asm volatile("red.global.add.v4.f32 [%0], {%1, %2, %3, %4};"
                             :: "l"(&orow[lane + 32 * j]),
                                "f"(v.x), "f"(v.y), "f"(v.z), "f"(v.w)
                             : "memory");
            }
        }
    }
}

// ---------------- launch ------------------------------------------------------
extern "C" void kernel_launch(void* const* d_in, const int* in_sizes, int n_in,
                              void* d_out, int out_size) {
    const float* uemb = (const float*)d_in[0];
    const float* iemb = (const float*)d_in[1];
    const int*   ei   = (const int*)d_in[2];
    const float* W1   = (const float*)d_in[3];
    const float* b1   = (const float*)d_in[4];
    const float* W2   = (const float*)d_in[5];
    const float* b2   = (const float*)d_in[6];
    const float* gW   = (const float*)d_in[7];
    const float* gb   = (const float*)d_in[8];

    int n_users = in_sizes[0] / HID;
    int n_items = in_sizes[1] / HID;
    int n_edges = in_sizes[2] / 2;
    int n_nodes = n_users + n_items;

    float* out_gcn  = (float*)d_out;
    float* out_edge = out_gcn + (size_t)n_nodes * HID;

    setup_kernel<<<(HID * HID) / 256, 256>>>(gW, n_nodes);

    int ublk = (n_users + ABM - 1) / ABM;
    int iblk = (n_items + ABM - 1) / ABM;
    attn_precompute_kernel<<<ublk + iblk, 256>>>(uemb, iemb, W1,
                                                 n_users, n_items, ublk);

    edge_weight_kernel<<<(n_edges + 255) / 256, 256>>>(ei, b1, W2, b2, n_edges);

    argmax_kernel<<<(n_edges + 255) / 256, 256>>>(n_edges);

    finalize_kernel<<<(n_edges + 255) / 256, 256>>>(ei, out_edge, n_edges);

    dim3 ggrid(MPAD / GBM, HID / GBN);
    gemm_bf16_kernel<<<ggrid, 256>>>(gb, out_gcn, n_nodes);

    scatter_kernel<<<1184, 256>>>(ei, out_edge, out_gcn, n_edges);
}